// round 1
// baseline (speedup 1.0000x reference)
#include <cuda_runtime.h>
#include <math.h>

// Problem constants
#define BSZ   4
#define SEQ   2048
#define DIM   1024
#define NH    16
#define HD    64
#define MTOT  (BSZ * SEQ)          // 8192 rows for all projections
#define SMSCALE 0.125f             // 1/sqrt(64)

// ---------------------------------------------------------------------------
// Scratch (device globals: allocation-guard safe)
// ---------------------------------------------------------------------------
__device__ float g_q [(size_t)MTOT * DIM];
__device__ float g_k [(size_t)MTOT * DIM];
__device__ float g_v [(size_t)MTOT * DIM];
__device__ float g_ao[(size_t)MTOT * DIM];

// ---------------------------------------------------------------------------
// GEMM: C[MTOT, DIM] = A[MTOT, DIM] @ W[DIM, DIM] + bias
// 128x128 block tile, BK=16, 256 threads, 8x8 per-thread micro-tile in the
// classic 4+4 split layout (conflict-free Bs reads, broadcast As reads).
// ---------------------------------------------------------------------------
__global__ __launch_bounds__(256) void gemm_bias_kernel(
    const float* __restrict__ A, const float* __restrict__ W,
    const float* __restrict__ bias, float* __restrict__ C)
{
    __shared__ float As[16][132];   // A tile, stored transposed [k][m]
    __shared__ float Bs[16][128];   // W tile [k][n]

    const int tid = threadIdx.x;
    const int tx  = tid & 15;       // column group
    const int ty  = tid >> 4;       // row group
    const int rbase = blockIdx.y * 128;
    const int cbase = blockIdx.x * 128;

    float acc[8][8];
#pragma unroll
    for (int i = 0; i < 8; i++)
#pragma unroll
        for (int j = 0; j < 8; j++) acc[i][j] = 0.f;

    for (int kb = 0; kb < DIM; kb += 16) {
        // Load A tile (128 rows x 16 cols), store transposed
#pragma unroll
        for (int it = 0; it < 2; it++) {
            int f   = tid + it * 256;          // 0..511 float4s
            int row = f >> 2;
            int c4  = f & 3;
            float4 v = *(const float4*)(A + (size_t)(rbase + row) * DIM + kb + c4 * 4);
            As[c4 * 4 + 0][row] = v.x;
            As[c4 * 4 + 1][row] = v.y;
            As[c4 * 4 + 2][row] = v.z;
            As[c4 * 4 + 3][row] = v.w;
        }
        // Load W tile (16 rows x 128 cols), direct
#pragma unroll
        for (int it = 0; it < 2; it++) {
            int f   = tid + it * 256;
            int row = f >> 5;
            int c4  = f & 31;
            *(float4*)(&Bs[row][c4 * 4]) =
                *(const float4*)(W + (size_t)(kb + row) * DIM + cbase + c4 * 4);
        }
        __syncthreads();

#pragma unroll
        for (int kk = 0; kk < 16; kk++) {
            float ra[8], rb[8];
            *(float4*)(ra)     = *(const float4*)(&As[kk][ty * 4]);
            *(float4*)(ra + 4) = *(const float4*)(&As[kk][64 + ty * 4]);
            *(float4*)(rb)     = *(const float4*)(&Bs[kk][tx * 4]);
            *(float4*)(rb + 4) = *(const float4*)(&Bs[kk][64 + tx * 4]);
#pragma unroll
            for (int i = 0; i < 8; i++)
#pragma unroll
                for (int j = 0; j < 8; j++)
                    acc[i][j] += ra[i] * rb[j];
        }
        __syncthreads();
    }

    // Epilogue: +bias, write out
#pragma unroll
    for (int i = 0; i < 8; i++) {
        int r = rbase + ((i < 4) ? (ty * 4 + i) : (64 + ty * 4 + (i - 4)));
#pragma unroll
        for (int jj = 0; jj < 2; jj++) {
            int c = cbase + jj * 64 + tx * 4;
            float4 bv = *(const float4*)(bias + c);
            float4 o;
            o.x = acc[i][jj * 4 + 0] + bv.x;
            o.y = acc[i][jj * 4 + 1] + bv.y;
            o.z = acc[i][jj * 4 + 2] + bv.z;
            o.w = acc[i][jj * 4 + 3] + bv.w;
            *(float4*)(C + (size_t)r * DIM + c) = o;
        }
    }
}

// ---------------------------------------------------------------------------
// Flash attention: one block per (b, h, 64-row q tile).
// Q/K/V stored as [bs*L, D] with head h at columns h*64..h*64+63.
// 256 threads; per-thread 4 q-rows (ty) x 4 k-cols / dk-cols (tx).
// Online softmax; P goes through smem for the PV product.
// ---------------------------------------------------------------------------
#define ATTN_PAD 68
#define ATTN_SMEM_BYTES ((4 * 64 * ATTN_PAD + 64) * (int)sizeof(float))

__global__ __launch_bounds__(256) void attn_kernel(
    const float* __restrict__ Q, const float* __restrict__ K,
    const float* __restrict__ V, const int* __restrict__ mask,
    float* __restrict__ O)
{
    extern __shared__ float sm[];
    float (*Qs)[ATTN_PAD] = (float(*)[ATTN_PAD])(sm);
    float (*Ks)[ATTN_PAD] = (float(*)[ATTN_PAD])(sm + 64 * ATTN_PAD);
    float (*Vs)[ATTN_PAD] = (float(*)[ATTN_PAD])(sm + 2 * 64 * ATTN_PAD);
    float (*Ps)[ATTN_PAD] = (float(*)[ATTN_PAD])(sm + 3 * 64 * ATTN_PAD);
    float* msk = sm + 4 * 64 * ATTN_PAD;

    const int tid = threadIdx.x;
    const int tx  = tid & 15;
    const int ty  = tid >> 4;
    const int qbase = blockIdx.x * 64;
    const int h = blockIdx.y;
    const int b = blockIdx.z;
    const size_t rowstart = ((size_t)b * SEQ) * DIM + (size_t)h * HD;

    // Load Q tile [64 q][64 d]
#pragma unroll
    for (int it = 0; it < 4; it++) {
        int f  = tid + it * 256;       // 0..1023 float4s
        int qq = f >> 4;
        int d4 = f & 15;
        *(float4*)(&Qs[qq][d4 * 4]) =
            *(const float4*)(Q + rowstart + (size_t)(qbase + qq) * DIM + d4 * 4);
    }

    float o[4][4];
    float m_run[4], l_run[4];
#pragma unroll
    for (int i = 0; i < 4; i++) {
        m_run[i] = -3.0e38f;
        l_run[i] = 0.f;
#pragma unroll
        for (int j = 0; j < 4; j++) o[i][j] = 0.f;
    }

    for (int kt = 0; kt < SEQ / 64; kt++) {
        const int kbase = kt * 64;
        // Load K,V tiles [64 k][64 d]
#pragma unroll
        for (int it = 0; it < 4; it++) {
            int f  = tid + it * 256;
            int kk = f >> 4;
            int d4 = f & 15;
            *(float4*)(&Ks[kk][d4 * 4]) =
                *(const float4*)(K + rowstart + (size_t)(kbase + kk) * DIM + d4 * 4);
            *(float4*)(&Vs[kk][d4 * 4]) =
                *(const float4*)(V + rowstart + (size_t)(kbase + kk) * DIM + d4 * 4);
        }
        if (tid < 64)
            msk[tid] = (mask[b * SEQ + kbase + tid] != 0) ? 1.0f : 0.0f;
        __syncthreads();

        // S = Q . K^T (4x4 per thread)
        float s[4][4];
#pragma unroll
        for (int i = 0; i < 4; i++)
#pragma unroll
            for (int j = 0; j < 4; j++) s[i][j] = 0.f;

#pragma unroll
        for (int d4 = 0; d4 < 16; d4++) {
            float4 qv[4], kv[4];
#pragma unroll
            for (int i = 0; i < 4; i++) qv[i] = *(const float4*)(&Qs[ty * 4 + i][d4 * 4]);
#pragma unroll
            for (int j = 0; j < 4; j++) kv[j] = *(const float4*)(&Ks[tx * 4 + j][d4 * 4]);
#pragma unroll
            for (int i = 0; i < 4; i++)
#pragma unroll
                for (int j = 0; j < 4; j++)
                    s[i][j] += qv[i].x * kv[j].x + qv[i].y * kv[j].y
                             + qv[i].z * kv[j].z + qv[i].w * kv[j].w;
        }

        // scale + key padding mask (masked -> exactly -1e30, matching ref)
        float km[4];
#pragma unroll
        for (int j = 0; j < 4; j++) km[j] = msk[tx * 4 + j];
#pragma unroll
        for (int i = 0; i < 4; i++)
#pragma unroll
            for (int j = 0; j < 4; j++)
                s[i][j] = (km[j] > 0.5f) ? -1.0e30f : s[i][j] * SMSCALE;

        // row max across this tile
        float mt[4];
#pragma unroll
        for (int i = 0; i < 4; i++) {
            mt[i] = fmaxf(fmaxf(s[i][0], s[i][1]), fmaxf(s[i][2], s[i][3]));
        }
#pragma unroll
        for (int off = 8; off >= 1; off >>= 1)
#pragma unroll
            for (int i = 0; i < 4; i++)
                mt[i] = fmaxf(mt[i], __shfl_xor_sync(0xffffffffu, mt[i], off));

        float m_new[4], alpha[4];
#pragma unroll
        for (int i = 0; i < 4; i++) {
            m_new[i] = fmaxf(m_run[i], mt[i]);
            alpha[i] = __expf(m_run[i] - m_new[i]);
        }

        // p = exp(s - m_new); tile row sums
        float lt[4] = {0.f, 0.f, 0.f, 0.f};
#pragma unroll
        for (int i = 0; i < 4; i++)
#pragma unroll
            for (int j = 0; j < 4; j++) {
                float p = __expf(s[i][j] - m_new[i]);
                s[i][j] = p;
                lt[i] += p;
            }
#pragma unroll
        for (int off = 8; off >= 1; off >>= 1)
#pragma unroll
            for (int i = 0; i < 4; i++)
                lt[i] += __shfl_xor_sync(0xffffffffu, lt[i], off);

#pragma unroll
        for (int i = 0; i < 4; i++) {
            l_run[i] = l_run[i] * alpha[i] + lt[i];
            m_run[i] = m_new[i];
#pragma unroll
            for (int j = 0; j < 4; j++) o[i][j] *= alpha[i];
        }

        // stage P to smem
#pragma unroll
        for (int i = 0; i < 4; i++) {
            float4 pw = make_float4(s[i][0], s[i][1], s[i][2], s[i][3]);
            *(float4*)(&Ps[ty * 4 + i][tx * 4]) = pw;
        }
        __syncthreads();

        // O += P @ V  (rows = q (ty), cols = dk (tx))
#pragma unroll
        for (int k4 = 0; k4 < 16; k4++) {
            float pr[4][4];
#pragma unroll
            for (int i = 0; i < 4; i++) {
                float4 t = *(const float4*)(&Ps[ty * 4 + i][k4 * 4]);
                pr[i][0] = t.x; pr[i][1] = t.y; pr[i][2] = t.z; pr[i][3] = t.w;
            }
#pragma unroll
            for (int u = 0; u < 4; u++) {
                float4 vv = *(const float4*)(&Vs[k4 * 4 + u][tx * 4]);
#pragma unroll
                for (int i = 0; i < 4; i++) {
                    o[i][0] += pr[i][u] * vv.x;
                    o[i][1] += pr[i][u] * vv.y;
                    o[i][2] += pr[i][u] * vv.z;
                    o[i][3] += pr[i][u] * vv.w;
                }
            }
        }
        __syncthreads();  // protect Ks/Vs/Ps before next tile
    }

    // normalize + write attn output at [b, q, h*64 + dk]
#pragma unroll
    for (int i = 0; i < 4; i++) {
        float inv = 1.0f / l_run[i];
        int q = qbase + ty * 4 + i;
        float4 ov = make_float4(o[i][0] * inv, o[i][1] * inv,
                                o[i][2] * inv, o[i][3] * inv);
        *(float4*)(O + rowstart + (size_t)q * DIM + tx * 4) = ov;
    }
}

// ---------------------------------------------------------------------------
// Launch
// ---------------------------------------------------------------------------
extern "C" void kernel_launch(void* const* d_in, const int* in_sizes, int n_in,
                              void* d_out, int out_size)
{
    const float* x    = (const float*)d_in[0];
    const int*   mask = (const int*)  d_in[1];
    const float* Wq   = (const float*)d_in[2];
    const float* bq   = (const float*)d_in[3];
    const float* Wk   = (const float*)d_in[4];
    const float* bk   = (const float*)d_in[5];
    const float* Wv   = (const float*)d_in[6];
    const float* bv   = (const float*)d_in[7];
    const float* Wf   = (const float*)d_in[8];
    const float* bf   = (const float*)d_in[9];
    float* out = (float*)d_out;

    float *q, *k, *v, *ao;
    cudaGetSymbolAddress((void**)&q,  g_q);
    cudaGetSymbolAddress((void**)&k,  g_k);
    cudaGetSymbolAddress((void**)&v,  g_v);
    cudaGetSymbolAddress((void**)&ao, g_ao);

    dim3 ggrid(DIM / 128, MTOT / 128);   // (8, 64)
    gemm_bias_kernel<<<ggrid, 256>>>(x, Wq, bq, q);
    gemm_bias_kernel<<<ggrid, 256>>>(x, Wk, bk, k);
    gemm_bias_kernel<<<ggrid, 256>>>(x, Wv, bv, v);

    cudaFuncSetAttribute(attn_kernel,
                         cudaFuncAttributeMaxDynamicSharedMemorySize,
                         ATTN_SMEM_BYTES);
    attn_kernel<<<dim3(SEQ / 64, NH, BSZ), 256, ATTN_SMEM_BYTES>>>(q, k, v, mask, ao);

    gemm_bias_kernel<<<ggrid, 256>>>(ao, Wf, bf, out);
}

// round 3
// speedup vs baseline: 1.2757x; 1.2757x over previous
#include <cuda_runtime.h>
#include <cuda_bf16.h>
#include <stdint.h>
#include <math.h>

// Problem constants
#define BSZ   4
#define SEQ   2048
#define DIM   1024
#define NH    16
#define HD    64
#define MTOT  (BSZ * SEQ)          // 8192
#define SMSCALE 0.125f

// ---------------------------------------------------------------------------
// Scratch (device globals: allocation-guard safe)
// ---------------------------------------------------------------------------
__device__ float g_q [(size_t)MTOT * DIM];
__device__ float g_k [(size_t)MTOT * DIM];
__device__ float g_v [(size_t)MTOT * DIM];
__device__ float g_ao[(size_t)MTOT * DIM];
__device__ __nv_bfloat16 g_xh [(size_t)MTOT * DIM];
__device__ __nv_bfloat16 g_xl [(size_t)MTOT * DIM];
__device__ __nv_bfloat16 g_wth[(size_t)DIM * DIM];
__device__ __nv_bfloat16 g_wtl[(size_t)DIM * DIM];

// ---------------------------------------------------------------------------
// PTX helpers — portable sm_80+ instructions only (harness targets sm_100,
// no 'a' feature set, so no tcgen05/TMEM).
// ---------------------------------------------------------------------------
__device__ __forceinline__ uint32_t smem_u32(const void* p) {
    uint32_t a;
    asm("{ .reg .u64 t; cvta.to.shared.u64 t, %1; cvt.u32.u64 %0, t; }"
        : "=r"(a) : "l"(p));
    return a;
}

#define CP_ASYNC16(dst, src) \
    asm volatile("cp.async.cg.shared.global [%0], [%1], 16;" \
                 :: "r"(dst), "l"(src))
#define CP_COMMIT() asm volatile("cp.async.commit_group;" ::: "memory")
#define CP_WAIT(N)  asm volatile("cp.async.wait_group %0;" :: "n"(N) : "memory")

#define LDSM_X4(R, addr) \
    asm volatile("ldmatrix.sync.aligned.m8n8.x4.shared.b16 {%0,%1,%2,%3}, [%4];" \
                 : "=r"((R)[0]), "=r"((R)[1]), "=r"((R)[2]), "=r"((R)[3]) \
                 : "r"(addr))

#define MMA_BF16(D, A, B0, B1) \
    asm volatile("mma.sync.aligned.m16n8k16.row.col.f32.bf16.bf16.f32 " \
                 "{%0,%1,%2,%3}, {%4,%5,%6,%7}, {%8,%9}, {%0,%1,%2,%3};" \
                 : "+f"((D)[0]), "+f"((D)[1]), "+f"((D)[2]), "+f"((D)[3]) \
                 : "r"((A)[0]), "r"((A)[1]), "r"((A)[2]), "r"((A)[3]), \
                   "r"(B0), "r"(B1))

// ---------------------------------------------------------------------------
// split fp32 -> (hi, lo) bf16
// ---------------------------------------------------------------------------
__global__ __launch_bounds__(256) void split_kernel(
    const float* __restrict__ src, __nv_bfloat16* __restrict__ hi,
    __nv_bfloat16* __restrict__ lo, int n4)
{
    int i = blockIdx.x * 256 + threadIdx.x;
    if (i >= n4) return;
    float4 v = ((const float4*)src)[i];
    __nv_bfloat16 h0 = __float2bfloat16(v.x), h1 = __float2bfloat16(v.y);
    __nv_bfloat16 h2 = __float2bfloat16(v.z), h3 = __float2bfloat16(v.w);
    __nv_bfloat16 l0 = __float2bfloat16(v.x - __bfloat162float(h0));
    __nv_bfloat16 l1 = __float2bfloat16(v.y - __bfloat162float(h1));
    __nv_bfloat16 l2 = __float2bfloat16(v.z - __bfloat162float(h2));
    __nv_bfloat16 l3 = __float2bfloat16(v.w - __bfloat162float(h3));
    ((__nv_bfloat162*)hi)[2 * i]     = __nv_bfloat162(h0, h1);
    ((__nv_bfloat162*)hi)[2 * i + 1] = __nv_bfloat162(h2, h3);
    ((__nv_bfloat162*)lo)[2 * i]     = __nv_bfloat162(l0, l1);
    ((__nv_bfloat162*)lo)[2 * i + 1] = __nv_bfloat162(l2, l3);
}

// ---------------------------------------------------------------------------
// transpose + split: Th[n][k] = bf16_hi(W[k][n]), Tl likewise
// ---------------------------------------------------------------------------
__global__ __launch_bounds__(256) void trsplit_kernel(
    const float* __restrict__ W, __nv_bfloat16* __restrict__ Th,
    __nv_bfloat16* __restrict__ Tl)
{
    __shared__ float t[32][33];
    int bx = blockIdx.x * 32, by = blockIdx.y * 32;
    int tx = threadIdx.x, ty = threadIdx.y;   // (32, 8)
#pragma unroll
    for (int j = 0; j < 4; j++)
        t[ty + j * 8][tx] = W[(size_t)(by + ty + j * 8) * DIM + bx + tx];
    __syncthreads();
#pragma unroll
    for (int j = 0; j < 4; j++) {
        float v = t[tx][ty + j * 8];
        __nv_bfloat16 h = __float2bfloat16(v);
        __nv_bfloat16 l = __float2bfloat16(v - __bfloat162float(h));
        size_t o = (size_t)(bx + ty + j * 8) * DIM + by + tx;
        Th[o] = h;
        Tl[o] = l;
    }
}

// ---------------------------------------------------------------------------
// mma.sync split-bf16 GEMM: C[MTOT,DIM] = A @ Wt^T + bias
// 128x128 CTA tile, BK=64, 8 warps (2x4), warp tile 64x32 (4x4 m16n8k16).
// SMEM stage: Ah|Al|Bh|Bl 16KB each; double-buffered via cp.async.
// Rows are 128B, SW128 swizzle: chunk' = chunk ^ (row&7) -> conflict-free
// ldmatrix and cp.async stores.
// ---------------------------------------------------------------------------
#define GT_TILE   16384
#define GT_STAGE  (4 * GT_TILE)     // 64 KB
#define GEMM_SMEM (2 * GT_STAGE)    // 128 KB

__global__ __launch_bounds__(256, 1) void gemm_mma_kernel(
    const __nv_bfloat16* __restrict__ Ahp, const __nv_bfloat16* __restrict__ Alp,
    const __nv_bfloat16* __restrict__ Bhp, const __nv_bfloat16* __restrict__ Blp,
    const float* __restrict__ bias, float* __restrict__ C)
{
    extern __shared__ char smem[];
    const uint32_t sb = smem_u32(smem);
    const int tid  = threadIdx.x;
    const int lane = tid & 31;
    const int warp = tid >> 5;
    const int wm   = warp >> 2;      // 0..1 (64 rows each)
    const int wn   = warp & 3;       // 0..3 (32 cols each)
    const int rbase = blockIdx.y * 128;
    const int cbase = blockIdx.x * 128;

    // cp.async source/dst mapping: 4 iters x 256 threads = 1024 16B-chunks/tile
    const int ldrow = tid >> 3;        // base row (advance by 32 per iter)
    const int ldc8  = tid & 7;         // 16B chunk within 128B row

    const __nv_bfloat16* srcs[4] = {Ahp, Alp, Bhp, Blp};

#define ISSUE_STAGE(KB, BUF)                                                     \
    do {                                                                         \
        uint32_t _sbase = sb + (BUF) * GT_STAGE;                                 \
        _Pragma("unroll")                                                        \
        for (int t4 = 0; t4 < 4; t4++) {                                         \
            const __nv_bfloat16* _S = srcs[t4];                                  \
            int _rb = (t4 < 2) ? rbase : cbase;                                  \
            _Pragma("unroll")                                                    \
            for (int it = 0; it < 4; it++) {                                     \
                int _row = ldrow + it * 32;                                      \
                uint32_t _dst = _sbase + t4 * GT_TILE + _row * 128               \
                              + ((ldc8 ^ (_row & 7)) << 4);                      \
                const __nv_bfloat16* _src = _S                                   \
                    + (size_t)(_rb + _row) * DIM + (KB) + ldc8 * 8;              \
                CP_ASYNC16(_dst, _src);                                          \
            }                                                                    \
        }                                                                        \
        CP_COMMIT();                                                             \
    } while (0)

    // ldmatrix per-thread geometry
    const uint32_t rA   = wm * 64 + (lane & 7) + ((lane >> 3) & 1) * 8; // +mt*16
    const uint32_t hiA  = lane >> 4;
    const uint32_t xorA = rA & 7;
    const uint32_t rB   = wn * 32 + (lane & 7) + (lane >> 4) * 8;       // +nb*16
    const uint32_t hiB  = (lane >> 3) & 1;
    const uint32_t xorB = rB & 7;

    float acc[4][4][4];
#pragma unroll
    for (int i = 0; i < 4; i++)
#pragma unroll
        for (int j = 0; j < 4; j++)
#pragma unroll
            for (int r = 0; r < 4; r++) acc[i][j][r] = 0.f;

    ISSUE_STAGE(0, 0);

    const int NK = DIM / 64;   // 16 chunks
    for (int kc = 0; kc < NK; kc++) {
        if (kc + 1 < NK) {
            ISSUE_STAGE((kc + 1) * 64, (kc + 1) & 1);
            CP_WAIT(1);
        } else {
            CP_WAIT(0);
        }
        __syncthreads();

        const uint32_t st = sb + (kc & 1) * GT_STAGE;
        const uint32_t sAh = st;
        const uint32_t sAl = st + GT_TILE;
        const uint32_t sBh = st + 2 * GT_TILE;
        const uint32_t sBl = st + 3 * GT_TILE;

#pragma unroll
        for (int ks = 0; ks < 4; ks++) {
            uint32_t ah[4][4], al[4][4], bh[2][4], bl[2][4];
            const uint32_t cA = ((2 * ks + hiA) ^ xorA) << 4;
            const uint32_t cB = ((2 * ks + hiB) ^ xorB) << 4;
#pragma unroll
            for (int mt = 0; mt < 4; mt++) {
                uint32_t ro = (rA + mt * 16) * 128;
                LDSM_X4(ah[mt], sAh + ro + cA);
                LDSM_X4(al[mt], sAl + ro + cA);
            }
#pragma unroll
            for (int nb = 0; nb < 2; nb++) {
                uint32_t ro = (rB + nb * 16) * 128;
                LDSM_X4(bh[nb], sBh + ro + cB);
                LDSM_X4(bl[nb], sBl + ro + cB);
            }
#pragma unroll
            for (int mt = 0; mt < 4; mt++)
#pragma unroll
                for (int nt = 0; nt < 4; nt++) {
                    const int nb = nt >> 1, p = (nt & 1) * 2;
                    MMA_BF16(acc[mt][nt], ah[mt], bh[nb][p], bh[nb][p + 1]);
                    MMA_BF16(acc[mt][nt], ah[mt], bl[nb][p], bl[nb][p + 1]);
                    MMA_BF16(acc[mt][nt], al[mt], bh[nb][p], bh[nb][p + 1]);
                }
        }
        __syncthreads();   // all warps done with this buffer before reuse
    }
#undef ISSUE_STAGE

    // Epilogue: +bias, write fp32
#pragma unroll
    for (int mt = 0; mt < 4; mt++) {
        const int row0 = rbase + wm * 64 + mt * 16 + (lane >> 2);
#pragma unroll
        for (int nt = 0; nt < 4; nt++) {
            const int col = cbase + wn * 32 + nt * 8 + (lane & 3) * 2;
            const float b0 = bias[col], b1 = bias[col + 1];
            float2 v0 = make_float2(acc[mt][nt][0] + b0, acc[mt][nt][1] + b1);
            float2 v1 = make_float2(acc[mt][nt][2] + b0, acc[mt][nt][3] + b1);
            *(float2*)(C + (size_t)row0 * DIM + col)       = v0;
            *(float2*)(C + (size_t)(row0 + 8) * DIM + col) = v1;
        }
    }
}

// ---------------------------------------------------------------------------
// Flash attention (round-1 version): one block per (b, h, 64-q tile)
// ---------------------------------------------------------------------------
#define ATTN_PAD 68
#define ATTN_SMEM_BYTES ((4 * 64 * ATTN_PAD + 64) * (int)sizeof(float))

__global__ __launch_bounds__(256) void attn_kernel(
    const float* __restrict__ Q, const float* __restrict__ K,
    const float* __restrict__ V, const int* __restrict__ mask,
    float* __restrict__ O)
{
    extern __shared__ float sm[];
    float (*Qs)[ATTN_PAD] = (float(*)[ATTN_PAD])(sm);
    float (*Ks)[ATTN_PAD] = (float(*)[ATTN_PAD])(sm + 64 * ATTN_PAD);
    float (*Vs)[ATTN_PAD] = (float(*)[ATTN_PAD])(sm + 2 * 64 * ATTN_PAD);
    float (*Ps)[ATTN_PAD] = (float(*)[ATTN_PAD])(sm + 3 * 64 * ATTN_PAD);
    float* msk = sm + 4 * 64 * ATTN_PAD;

    const int tid = threadIdx.x;
    const int tx  = tid & 15;
    const int ty  = tid >> 4;
    const int qbase = blockIdx.x * 64;
    const int h = blockIdx.y;
    const int b = blockIdx.z;
    const size_t rowstart = ((size_t)b * SEQ) * DIM + (size_t)h * HD;

#pragma unroll
    for (int it = 0; it < 4; it++) {
        int f  = tid + it * 256;
        int qq = f >> 4;
        int d4 = f & 15;
        *(float4*)(&Qs[qq][d4 * 4]) =
            *(const float4*)(Q + rowstart + (size_t)(qbase + qq) * DIM + d4 * 4);
    }

    float o[4][4];
    float m_run[4], l_run[4];
#pragma unroll
    for (int i = 0; i < 4; i++) {
        m_run[i] = -3.0e38f;
        l_run[i] = 0.f;
#pragma unroll
        for (int j = 0; j < 4; j++) o[i][j] = 0.f;
    }

    for (int kt = 0; kt < SEQ / 64; kt++) {
        const int kbase = kt * 64;
#pragma unroll
        for (int it = 0; it < 4; it++) {
            int f  = tid + it * 256;
            int kk = f >> 4;
            int d4 = f & 15;
            *(float4*)(&Ks[kk][d4 * 4]) =
                *(const float4*)(K + rowstart + (size_t)(kbase + kk) * DIM + d4 * 4);
            *(float4*)(&Vs[kk][d4 * 4]) =
                *(const float4*)(V + rowstart + (size_t)(kbase + kk) * DIM + d4 * 4);
        }
        if (tid < 64)
            msk[tid] = (mask[b * SEQ + kbase + tid] != 0) ? 1.0f : 0.0f;
        __syncthreads();

        float s[4][4];
#pragma unroll
        for (int i = 0; i < 4; i++)
#pragma unroll
            for (int j = 0; j < 4; j++) s[i][j] = 0.f;

#pragma unroll
        for (int d4 = 0; d4 < 16; d4++) {
            float4 qv[4], kv[4];
#pragma unroll
            for (int i = 0; i < 4; i++) qv[i] = *(const float4*)(&Qs[ty * 4 + i][d4 * 4]);
#pragma unroll
            for (int j = 0; j < 4; j++) kv[j] = *(const float4*)(&Ks[tx * 4 + j][d4 * 4]);
#pragma unroll
            for (int i = 0; i < 4; i++)
#pragma unroll
                for (int j = 0; j < 4; j++)
                    s[i][j] += qv[i].x * kv[j].x + qv[i].y * kv[j].y
                             + qv[i].z * kv[j].z + qv[i].w * kv[j].w;
        }

        float km[4];
#pragma unroll
        for (int j = 0; j < 4; j++) km[j] = msk[tx * 4 + j];
#pragma unroll
        for (int i = 0; i < 4; i++)
#pragma unroll
            for (int j = 0; j < 4; j++)
                s[i][j] = (km[j] > 0.5f) ? -1.0e30f : s[i][j] * SMSCALE;

        float mt[4];
#pragma unroll
        for (int i = 0; i < 4; i++)
            mt[i] = fmaxf(fmaxf(s[i][0], s[i][1]), fmaxf(s[i][2], s[i][3]));
#pragma unroll
        for (int off = 8; off >= 1; off >>= 1)
#pragma unroll
            for (int i = 0; i < 4; i++)
                mt[i] = fmaxf(mt[i], __shfl_xor_sync(0xffffffffu, mt[i], off));

        float m_new[4], alpha[4];
#pragma unroll
        for (int i = 0; i < 4; i++) {
            m_new[i] = fmaxf(m_run[i], mt[i]);
            alpha[i] = __expf(m_run[i] - m_new[i]);
        }

        float lt[4] = {0.f, 0.f, 0.f, 0.f};
#pragma unroll
        for (int i = 0; i < 4; i++)
#pragma unroll
            for (int j = 0; j < 4; j++) {
                float p = __expf(s[i][j] - m_new[i]);
                s[i][j] = p;
                lt[i] += p;
            }
#pragma unroll
        for (int off = 8; off >= 1; off >>= 1)
#pragma unroll
            for (int i = 0; i < 4; i++)
                lt[i] += __shfl_xor_sync(0xffffffffu, lt[i], off);

#pragma unroll
        for (int i = 0; i < 4; i++) {
            l_run[i] = l_run[i] * alpha[i] + lt[i];
            m_run[i] = m_new[i];
#pragma unroll
            for (int j = 0; j < 4; j++) o[i][j] *= alpha[i];
        }

#pragma unroll
        for (int i = 0; i < 4; i++) {
            float4 pw = make_float4(s[i][0], s[i][1], s[i][2], s[i][3]);
            *(float4*)(&Ps[ty * 4 + i][tx * 4]) = pw;
        }
        __syncthreads();

#pragma unroll
        for (int k4 = 0; k4 < 16; k4++) {
            float pr[4][4];
#pragma unroll
            for (int i = 0; i < 4; i++) {
                float4 t = *(const float4*)(&Ps[ty * 4 + i][k4 * 4]);
                pr[i][0] = t.x; pr[i][1] = t.y; pr[i][2] = t.z; pr[i][3] = t.w;
            }
#pragma unroll
            for (int u = 0; u < 4; u++) {
                float4 vv = *(const float4*)(&Vs[k4 * 4 + u][tx * 4]);
#pragma unroll
                for (int i = 0; i < 4; i++) {
                    o[i][0] += pr[i][u] * vv.x;
                    o[i][1] += pr[i][u] * vv.y;
                    o[i][2] += pr[i][u] * vv.z;
                    o[i][3] += pr[i][u] * vv.w;
                }
            }
        }
        __syncthreads();
    }

#pragma unroll
    for (int i = 0; i < 4; i++) {
        float inv = 1.0f / l_run[i];
        int q = qbase + ty * 4 + i;
        float4 ov = make_float4(o[i][0] * inv, o[i][1] * inv,
                                o[i][2] * inv, o[i][3] * inv);
        *(float4*)(O + rowstart + (size_t)q * DIM + tx * 4) = ov;
    }
}

// ---------------------------------------------------------------------------
// Launch
// ---------------------------------------------------------------------------
extern "C" void kernel_launch(void* const* d_in, const int* in_sizes, int n_in,
                              void* d_out, int out_size)
{
    const float* x    = (const float*)d_in[0];
    const int*   mask = (const int*)  d_in[1];
    const float* Wq   = (const float*)d_in[2];
    const float* bq   = (const float*)d_in[3];
    const float* Wk   = (const float*)d_in[4];
    const float* bk   = (const float*)d_in[5];
    const float* Wv   = (const float*)d_in[6];
    const float* bv   = (const float*)d_in[7];
    const float* Wf   = (const float*)d_in[8];
    const float* bf   = (const float*)d_in[9];
    float* out = (float*)d_out;

    float *q, *k, *v, *ao;
    __nv_bfloat16 *xh, *xl, *wth, *wtl;
    cudaGetSymbolAddress((void**)&q,   g_q);
    cudaGetSymbolAddress((void**)&k,   g_k);
    cudaGetSymbolAddress((void**)&v,   g_v);
    cudaGetSymbolAddress((void**)&ao,  g_ao);
    cudaGetSymbolAddress((void**)&xh,  g_xh);
    cudaGetSymbolAddress((void**)&xl,  g_xl);
    cudaGetSymbolAddress((void**)&wth, g_wth);
    cudaGetSymbolAddress((void**)&wtl, g_wtl);

    static bool attr_set = false;
    if (!attr_set) {
        cudaFuncSetAttribute(gemm_mma_kernel,
                             cudaFuncAttributeMaxDynamicSharedMemorySize, GEMM_SMEM);
        cudaFuncSetAttribute(attn_kernel,
                             cudaFuncAttributeMaxDynamicSharedMemorySize, ATTN_SMEM_BYTES);
        attr_set = true;
    }

    const int n4 = MTOT * DIM / 4;
    const dim3 trg(32, 32), trb(32, 8);
    const dim3 ggrid(DIM / 128, MTOT / 128);   // (8, 64)

    split_kernel<<<(n4 + 255) / 256, 256>>>(x, xh, xl, n4);

    trsplit_kernel<<<trg, trb>>>(Wq, wth, wtl);
    gemm_mma_kernel<<<ggrid, 256, GEMM_SMEM>>>(xh, xl, wth, wtl, bq, q);
    trsplit_kernel<<<trg, trb>>>(Wk, wth, wtl);
    gemm_mma_kernel<<<ggrid, 256, GEMM_SMEM>>>(xh, xl, wth, wtl, bk, k);
    trsplit_kernel<<<trg, trb>>>(Wv, wth, wtl);
    gemm_mma_kernel<<<ggrid, 256, GEMM_SMEM>>>(xh, xl, wth, wtl, bv, v);

    attn_kernel<<<dim3(SEQ / 64, NH, BSZ), 256, ATTN_SMEM_BYTES>>>(q, k, v, mask, ao);

    split_kernel<<<(n4 + 255) / 256, 256>>>(ao, xh, xl, n4);
    trsplit_kernel<<<trg, trb>>>(Wf, wth, wtl);
    gemm_mma_kernel<<<ggrid, 256, GEMM_SMEM>>>(xh, xl, wth, wtl, bf, out);
}

// round 4
// speedup vs baseline: 3.6744x; 2.8802x over previous
#include <cuda_runtime.h>
#include <cuda_bf16.h>
#include <stdint.h>
#include <math.h>

// Problem constants
#define BSZ   4
#define SEQ   2048
#define DIM   1024
#define NH    16
#define HD    64
#define MTOT  (BSZ * SEQ)          // 8192

// ---------------------------------------------------------------------------
// Scratch (device globals: allocation-guard safe)
// ---------------------------------------------------------------------------
__device__ float g_ao[(size_t)MTOT * DIM];
__device__ __nv_bfloat16 g_xh [(size_t)MTOT * DIM];
__device__ __nv_bfloat16 g_xl [(size_t)MTOT * DIM];
__device__ __nv_bfloat16 g_wth[(size_t)DIM * DIM];
__device__ __nv_bfloat16 g_wtl[(size_t)DIM * DIM];
__device__ __nv_bfloat16 g_qh [(size_t)MTOT * DIM];
__device__ __nv_bfloat16 g_ql [(size_t)MTOT * DIM];
__device__ __nv_bfloat16 g_kh [(size_t)MTOT * DIM];
__device__ __nv_bfloat16 g_kl [(size_t)MTOT * DIM];
__device__ __nv_bfloat16 g_vh [(size_t)MTOT * DIM];
__device__ __nv_bfloat16 g_vl [(size_t)MTOT * DIM];

// ---------------------------------------------------------------------------
// PTX helpers — portable sm_80+ only (harness targets plain sm_100)
// ---------------------------------------------------------------------------
__device__ __forceinline__ uint32_t smem_u32(const void* p) {
    uint32_t a;
    asm("{ .reg .u64 t; cvta.to.shared.u64 t, %1; cvt.u32.u64 %0, t; }"
        : "=r"(a) : "l"(p));
    return a;
}

#define CP_ASYNC16(dst, src) \
    asm volatile("cp.async.cg.shared.global [%0], [%1], 16;" \
                 :: "r"(dst), "l"(src))
#define CP_COMMIT() asm volatile("cp.async.commit_group;" ::: "memory")
#define CP_WAIT(N)  asm volatile("cp.async.wait_group %0;" :: "n"(N) : "memory")

#define LDSM_X4(R, addr) \
    asm volatile("ldmatrix.sync.aligned.m8n8.x4.shared.b16 {%0,%1,%2,%3}, [%4];" \
                 : "=r"((R)[0]), "=r"((R)[1]), "=r"((R)[2]), "=r"((R)[3]) \
                 : "r"(addr))
#define LDSM_X4_T(R, addr) \
    asm volatile("ldmatrix.sync.aligned.m8n8.x4.trans.shared.b16 {%0,%1,%2,%3}, [%4];" \
                 : "=r"((R)[0]), "=r"((R)[1]), "=r"((R)[2]), "=r"((R)[3]) \
                 : "r"(addr))

#define MMA_BF16(D, A, B0, B1) \
    asm volatile("mma.sync.aligned.m16n8k16.row.col.f32.bf16.bf16.f32 " \
                 "{%0,%1,%2,%3}, {%4,%5,%6,%7}, {%8,%9}, {%0,%1,%2,%3};" \
                 : "+f"((D)[0]), "+f"((D)[1]), "+f"((D)[2]), "+f"((D)[3]) \
                 : "r"((A)[0]), "r"((A)[1]), "r"((A)[2]), "r"((A)[3]), \
                   "r"(B0), "r"(B1))

__device__ __forceinline__ uint32_t pack_bf2(float lo, float hi) {
    __nv_bfloat162 t(__float2bfloat16(lo), __float2bfloat16(hi));
    return *(uint32_t*)&t;
}
__device__ __forceinline__ float bf_res(float f) {
    return f - __bfloat162float(__float2bfloat16(f));
}

// ---------------------------------------------------------------------------
// split fp32 -> (hi, lo) bf16
// ---------------------------------------------------------------------------
__global__ __launch_bounds__(256) void split_kernel(
    const float* __restrict__ src, __nv_bfloat16* __restrict__ hi,
    __nv_bfloat16* __restrict__ lo, int n4)
{
    int i = blockIdx.x * 256 + threadIdx.x;
    if (i >= n4) return;
    float4 v = ((const float4*)src)[i];
    __nv_bfloat16 h0 = __float2bfloat16(v.x), h1 = __float2bfloat16(v.y);
    __nv_bfloat16 h2 = __float2bfloat16(v.z), h3 = __float2bfloat16(v.w);
    __nv_bfloat16 l0 = __float2bfloat16(v.x - __bfloat162float(h0));
    __nv_bfloat16 l1 = __float2bfloat16(v.y - __bfloat162float(h1));
    __nv_bfloat16 l2 = __float2bfloat16(v.z - __bfloat162float(h2));
    __nv_bfloat16 l3 = __float2bfloat16(v.w - __bfloat162float(h3));
    ((__nv_bfloat162*)hi)[2 * i]     = __nv_bfloat162(h0, h1);
    ((__nv_bfloat162*)hi)[2 * i + 1] = __nv_bfloat162(h2, h3);
    ((__nv_bfloat162*)lo)[2 * i]     = __nv_bfloat162(l0, l1);
    ((__nv_bfloat162*)lo)[2 * i + 1] = __nv_bfloat162(l2, l3);
}

// ---------------------------------------------------------------------------
// transpose + split: Th[n][k] = bf16_hi(W[k][n]), Tl likewise
// ---------------------------------------------------------------------------
__global__ __launch_bounds__(256) void trsplit_kernel(
    const float* __restrict__ W, __nv_bfloat16* __restrict__ Th,
    __nv_bfloat16* __restrict__ Tl)
{
    __shared__ float t[32][33];
    int bx = blockIdx.x * 32, by = blockIdx.y * 32;
    int tx = threadIdx.x, ty = threadIdx.y;   // (32, 8)
#pragma unroll
    for (int j = 0; j < 4; j++)
        t[ty + j * 8][tx] = W[(size_t)(by + ty + j * 8) * DIM + bx + tx];
    __syncthreads();
#pragma unroll
    for (int j = 0; j < 4; j++) {
        float v = t[tx][ty + j * 8];
        __nv_bfloat16 h = __float2bfloat16(v);
        __nv_bfloat16 l = __float2bfloat16(v - __bfloat162float(h));
        size_t o = (size_t)(bx + ty + j * 8) * DIM + by + tx;
        Th[o] = h;
        Tl[o] = l;
    }
}

// ---------------------------------------------------------------------------
// mma.sync split-bf16 GEMM (from R3, verified). mode 0: fp32 out.
// mode 1: write (hi, lo) bf16 of scale*(acc+bias) to Chi/Clo.
// ---------------------------------------------------------------------------
#define GT_TILE   16384
#define GT_STAGE  (4 * GT_TILE)     // 64 KB
#define GEMM_SMEM (2 * GT_STAGE)    // 128 KB

__global__ __launch_bounds__(256, 1) void gemm_mma_kernel(
    const __nv_bfloat16* __restrict__ Ahp, const __nv_bfloat16* __restrict__ Alp,
    const __nv_bfloat16* __restrict__ Bhp, const __nv_bfloat16* __restrict__ Blp,
    const float* __restrict__ bias, float* __restrict__ C,
    __nv_bfloat16* __restrict__ Chi, __nv_bfloat16* __restrict__ Clo,
    int mode, float scale)
{
    extern __shared__ char smem[];
    const uint32_t sb = smem_u32(smem);
    const int tid  = threadIdx.x;
    const int lane = tid & 31;
    const int warp = tid >> 5;
    const int wm   = warp >> 2;
    const int wn   = warp & 3;
    const int rbase = blockIdx.y * 128;
    const int cbase = blockIdx.x * 128;

    const int ldrow = tid >> 3;
    const int ldc8  = tid & 7;
    const __nv_bfloat16* srcs[4] = {Ahp, Alp, Bhp, Blp};

#define ISSUE_STAGE(KB, BUF)                                                     \
    do {                                                                         \
        uint32_t _sbase = sb + (BUF) * GT_STAGE;                                 \
        _Pragma("unroll")                                                        \
        for (int t4 = 0; t4 < 4; t4++) {                                         \
            const __nv_bfloat16* _S = srcs[t4];                                  \
            int _rb = (t4 < 2) ? rbase : cbase;                                  \
            _Pragma("unroll")                                                    \
            for (int it = 0; it < 4; it++) {                                     \
                int _row = ldrow + it * 32;                                      \
                uint32_t _dst = _sbase + t4 * GT_TILE + _row * 128               \
                              + ((ldc8 ^ (_row & 7)) << 4);                      \
                const __nv_bfloat16* _src = _S                                   \
                    + (size_t)(_rb + _row) * DIM + (KB) + ldc8 * 8;              \
                CP_ASYNC16(_dst, _src);                                          \
            }                                                                    \
        }                                                                        \
        CP_COMMIT();                                                             \
    } while (0)

    const uint32_t rA   = wm * 64 + (lane & 7) + ((lane >> 3) & 1) * 8;
    const uint32_t hiA  = lane >> 4;
    const uint32_t xorA = rA & 7;
    const uint32_t rB   = wn * 32 + (lane & 7) + (lane >> 4) * 8;
    const uint32_t hiB  = (lane >> 3) & 1;
    const uint32_t xorB = rB & 7;

    float acc[4][4][4];
#pragma unroll
    for (int i = 0; i < 4; i++)
#pragma unroll
        for (int j = 0; j < 4; j++)
#pragma unroll
            for (int r = 0; r < 4; r++) acc[i][j][r] = 0.f;

    ISSUE_STAGE(0, 0);

    const int NK = DIM / 64;
    for (int kc = 0; kc < NK; kc++) {
        if (kc + 1 < NK) {
            ISSUE_STAGE((kc + 1) * 64, (kc + 1) & 1);
            CP_WAIT(1);
        } else {
            CP_WAIT(0);
        }
        __syncthreads();

        const uint32_t st = sb + (kc & 1) * GT_STAGE;
        const uint32_t sAh = st;
        const uint32_t sAl = st + GT_TILE;
        const uint32_t sBh = st + 2 * GT_TILE;
        const uint32_t sBl = st + 3 * GT_TILE;

#pragma unroll
        for (int ks = 0; ks < 4; ks++) {
            uint32_t ah[4][4], al[4][4], bh[2][4], bl[2][4];
            const uint32_t cA = ((2 * ks + hiA) ^ xorA) << 4;
            const uint32_t cB = ((2 * ks + hiB) ^ xorB) << 4;
#pragma unroll
            for (int mt = 0; mt < 4; mt++) {
                uint32_t ro = (rA + mt * 16) * 128;
                LDSM_X4(ah[mt], sAh + ro + cA);
                LDSM_X4(al[mt], sAl + ro + cA);
            }
#pragma unroll
            for (int nb = 0; nb < 2; nb++) {
                uint32_t ro = (rB + nb * 16) * 128;
                LDSM_X4(bh[nb], sBh + ro + cB);
                LDSM_X4(bl[nb], sBl + ro + cB);
            }
#pragma unroll
            for (int mt = 0; mt < 4; mt++)
#pragma unroll
                for (int nt = 0; nt < 4; nt++) {
                    const int nb = nt >> 1, p = (nt & 1) * 2;
                    MMA_BF16(acc[mt][nt], ah[mt], bh[nb][p], bh[nb][p + 1]);
                    MMA_BF16(acc[mt][nt], ah[mt], bl[nb][p], bl[nb][p + 1]);
                    MMA_BF16(acc[mt][nt], al[mt], bh[nb][p], bh[nb][p + 1]);
                }
        }
        __syncthreads();
    }
#undef ISSUE_STAGE

#pragma unroll
    for (int mt = 0; mt < 4; mt++) {
        const int row0 = rbase + wm * 64 + mt * 16 + (lane >> 2);
#pragma unroll
        for (int nt = 0; nt < 4; nt++) {
            const int col = cbase + wn * 32 + nt * 8 + (lane & 3) * 2;
            const float b0 = bias[col], b1 = bias[col + 1];
            float v00 = acc[mt][nt][0] + b0, v01 = acc[mt][nt][1] + b1;
            float v10 = acc[mt][nt][2] + b0, v11 = acc[mt][nt][3] + b1;
            if (mode == 0) {
                *(float2*)(C + (size_t)row0 * DIM + col)       = make_float2(v00, v01);
                *(float2*)(C + (size_t)(row0 + 8) * DIM + col) = make_float2(v10, v11);
            } else {
                v00 *= scale; v01 *= scale; v10 *= scale; v11 *= scale;
                __nv_bfloat16 h00 = __float2bfloat16(v00), h01 = __float2bfloat16(v01);
                __nv_bfloat16 h10 = __float2bfloat16(v10), h11 = __float2bfloat16(v11);
                *(__nv_bfloat162*)(Chi + (size_t)row0 * DIM + col) = __nv_bfloat162(h00, h01);
                *(__nv_bfloat162*)(Chi + (size_t)(row0 + 8) * DIM + col) = __nv_bfloat162(h10, h11);
                *(__nv_bfloat162*)(Clo + (size_t)row0 * DIM + col) =
                    __nv_bfloat162(__float2bfloat16(v00 - __bfloat162float(h00)),
                                   __float2bfloat16(v01 - __bfloat162float(h01)));
                *(__nv_bfloat162*)(Clo + (size_t)(row0 + 8) * DIM + col) =
                    __nv_bfloat162(__float2bfloat16(v10 - __bfloat162float(h10)),
                                   __float2bfloat16(v11 - __bfloat162float(h11)));
            }
        }
    }
}

// ---------------------------------------------------------------------------
// Tensor-core flash attention.
// CTA = (q-tile of 128, head, batch); 8 warps, warp = 16 q rows.
// K-loop over 64-key tiles; split-bf16 S and PV (3 terms each).
// Q already scaled by 1/8 (folded at projection).
// ---------------------------------------------------------------------------
#define A_BM 128
#define A_BN 64
#define A_NT (SEQ / A_BN)     // 32
// smem layout (bytes)
#define AQ_H   0
#define AQ_L   16384
#define AKV    32768          // 2 stages x (Kh|Kl|Vh|Vl, 8KB each) = 65536
#define AMSK   98304          // 2 x 64 floats
#define ATTN_SMEM (98304 + 512)

__global__ __launch_bounds__(256, 1) void attn_mma_kernel(
    const __nv_bfloat16* __restrict__ Qh, const __nv_bfloat16* __restrict__ Ql,
    const __nv_bfloat16* __restrict__ Kh, const __nv_bfloat16* __restrict__ Kl,
    const __nv_bfloat16* __restrict__ Vh, const __nv_bfloat16* __restrict__ Vl,
    const int* __restrict__ mask, float* __restrict__ O)
{
    extern __shared__ char smem[];
    const uint32_t sb = smem_u32(smem);
    const int tid  = threadIdx.x;
    const int lane = tid & 31;
    const int w    = tid >> 5;
    const int qbase = blockIdx.x * A_BM;
    const int h = blockIdx.y;
    const int b = blockIdx.z;

    const size_t hoff = (size_t)h * HD;
    const __nv_bfloat16* qhb = Qh + ((size_t)(b * SEQ + qbase)) * DIM + hoff;
    const __nv_bfloat16* qlb = Ql + ((size_t)(b * SEQ + qbase)) * DIM + hoff;
    const __nv_bfloat16* khb = Kh + ((size_t)b * SEQ) * DIM + hoff;
    const __nv_bfloat16* klb = Kl + ((size_t)b * SEQ) * DIM + hoff;
    const __nv_bfloat16* vhb = Vh + ((size_t)b * SEQ) * DIM + hoff;
    const __nv_bfloat16* vlb = Vl + ((size_t)b * SEQ) * DIM + hoff;

    const int ldrow = tid >> 3;     // 0..31
    const int ldc8  = tid & 7;

    // Q tiles (once): 128 rows x 128B, hi & lo
#pragma unroll
    for (int t = 0; t < 2; t++) {
        const __nv_bfloat16* src = t ? qlb : qhb;
        uint32_t dstb = sb + (t ? AQ_L : AQ_H);
#pragma unroll
        for (int it = 0; it < 4; it++) {
            int row = ldrow + it * 32;
            uint32_t dst = dstb + row * 128 + ((ldc8 ^ (row & 7)) << 4);
            CP_ASYNC16(dst, src + (size_t)row * DIM + ldc8 * 8);
        }
    }
    CP_COMMIT();

#define ISSUE_KV(KT, BUF)                                                        \
    do {                                                                         \
        int _kb = (KT) * A_BN;                                                   \
        uint32_t _db = sb + AKV + (BUF) * 32768;                                 \
        const __nv_bfloat16* _sp[4] = {khb, klb, vhb, vlb};                      \
        _Pragma("unroll")                                                        \
        for (int t4 = 0; t4 < 4; t4++) {                                         \
            _Pragma("unroll")                                                    \
            for (int it = 0; it < 2; it++) {                                     \
                int _row = ldrow + it * 32;                                      \
                uint32_t _dst = _db + t4 * 8192 + _row * 128                     \
                              + ((ldc8 ^ (_row & 7)) << 4);                      \
                CP_ASYNC16(_dst, _sp[t4] + (size_t)(_kb + _row) * DIM + ldc8 * 8); \
            }                                                                    \
        }                                                                        \
        CP_COMMIT();                                                             \
    } while (0)

    float* msks = (float*)(smem + AMSK);

    ISSUE_KV(0, 0);
    if (tid < 64)
        msks[tid] = (mask[b * SEQ + tid] != 0) ? 1.0f : 0.0f;
    CP_WAIT(0);
    __syncthreads();

    float o[8][4];
#pragma unroll
    for (int i = 0; i < 8; i++)
#pragma unroll
        for (int j = 0; j < 4; j++) o[i][j] = 0.f;
    float m_run0 = -3.0e38f, m_run1 = -3.0e38f;
    float l_run0 = 0.f, l_run1 = 0.f;

    const uint32_t rowA = w * 16 + (lane & 7) + ((lane >> 3) & 1) * 8;
    const uint32_t hiA  = lane >> 4;
    const uint32_t rowB = (lane & 7) + (lane >> 4) * 8;     // + nt2*16
    const uint32_t hiB  = (lane >> 3) & 1;
    const uint32_t rowV = (lane & 7) + ((lane >> 3) & 1) * 8; // + kc*16
    const uint32_t hiV  = lane >> 4;

    for (int kt = 0; kt < A_NT; kt++) {
        const int buf = kt & 1;
        if (kt + 1 < A_NT) {
            ISSUE_KV(kt + 1, 1 - buf);
            if (tid < 64)
                msks[(1 - buf) * 64 + tid] =
                    (mask[b * SEQ + (kt + 1) * A_BN + tid] != 0) ? 1.0f : 0.0f;
            CP_WAIT(1);
        } else {
            CP_WAIT(0);
        }
        __syncthreads();

        const uint32_t kvb = sb + AKV + buf * 32768;
        const uint32_t skh = kvb, skl = kvb + 8192;
        const uint32_t svh = kvb + 16384, svl = kvb + 24576;

        // ---- S = Q.K^T (pre-scaled by 1/8 via Q) ----
        float s[8][4];
#pragma unroll
        for (int i = 0; i < 8; i++)
#pragma unroll
            for (int j = 0; j < 4; j++) s[i][j] = 0.f;

#pragma unroll
        for (int kc = 0; kc < 4; kc++) {
            uint32_t qh4[4], ql4[4];
            const uint32_t cA = ((2 * kc + hiA) ^ (rowA & 7)) << 4;
            LDSM_X4(qh4, sb + AQ_H + rowA * 128 + cA);
            LDSM_X4(ql4, sb + AQ_L + rowA * 128 + cA);
#pragma unroll
            for (int nt2 = 0; nt2 < 4; nt2++) {
                const uint32_t rb = rowB + nt2 * 16;
                const uint32_t cB = ((2 * kc + hiB) ^ (rb & 7)) << 4;
                uint32_t kh4[4], kl4[4];
                LDSM_X4(kh4, skh + rb * 128 + cB);
                LDSM_X4(kl4, skl + rb * 128 + cB);
                MMA_BF16(s[nt2 * 2], qh4, kh4[0], kh4[1]);
                MMA_BF16(s[nt2 * 2], qh4, kl4[0], kl4[1]);
                MMA_BF16(s[nt2 * 2], ql4, kh4[0], kh4[1]);
                MMA_BF16(s[nt2 * 2 + 1], qh4, kh4[2], kh4[3]);
                MMA_BF16(s[nt2 * 2 + 1], qh4, kl4[2], kl4[3]);
                MMA_BF16(s[nt2 * 2 + 1], ql4, kh4[2], kh4[3]);
            }
        }

        // ---- mask + online softmax ----
        const float* mv = msks + buf * 64;
#pragma unroll
        for (int nt = 0; nt < 8; nt++) {
            int c0 = nt * 8 + (lane & 3) * 2;
            if (mv[c0]     > 0.5f) { s[nt][0] = -1.0e30f; s[nt][2] = -1.0e30f; }
            if (mv[c0 + 1] > 0.5f) { s[nt][1] = -1.0e30f; s[nt][3] = -1.0e30f; }
        }

        float mt0 = -3.0e38f, mt1 = -3.0e38f;
#pragma unroll
        for (int nt = 0; nt < 8; nt++) {
            mt0 = fmaxf(mt0, fmaxf(s[nt][0], s[nt][1]));
            mt1 = fmaxf(mt1, fmaxf(s[nt][2], s[nt][3]));
        }
        mt0 = fmaxf(mt0, __shfl_xor_sync(0xffffffffu, mt0, 1));
        mt0 = fmaxf(mt0, __shfl_xor_sync(0xffffffffu, mt0, 2));
        mt1 = fmaxf(mt1, __shfl_xor_sync(0xffffffffu, mt1, 1));
        mt1 = fmaxf(mt1, __shfl_xor_sync(0xffffffffu, mt1, 2));

        const float m_new0 = fmaxf(m_run0, mt0);
        const float m_new1 = fmaxf(m_run1, mt1);
        const float alpha0 = __expf(m_run0 - m_new0);
        const float alpha1 = __expf(m_run1 - m_new1);

#pragma unroll
        for (int nt = 0; nt < 8; nt++) {
            o[nt][0] *= alpha0; o[nt][1] *= alpha0;
            o[nt][2] *= alpha1; o[nt][3] *= alpha1;
        }

        float lt0 = 0.f, lt1 = 0.f;
#pragma unroll
        for (int nt = 0; nt < 8; nt++) {
            float p0 = __expf(s[nt][0] - m_new0);
            float p1 = __expf(s[nt][1] - m_new0);
            float p2 = __expf(s[nt][2] - m_new1);
            float p3 = __expf(s[nt][3] - m_new1);
            s[nt][0] = p0; s[nt][1] = p1; s[nt][2] = p2; s[nt][3] = p3;
            lt0 += p0 + p1; lt1 += p2 + p3;
        }
        lt0 += __shfl_xor_sync(0xffffffffu, lt0, 1);
        lt0 += __shfl_xor_sync(0xffffffffu, lt0, 2);
        lt1 += __shfl_xor_sync(0xffffffffu, lt1, 1);
        lt1 += __shfl_xor_sync(0xffffffffu, lt1, 2);

        l_run0 = l_run0 * alpha0 + lt0;
        l_run1 = l_run1 * alpha1 + lt1;
        m_run0 = m_new0;
        m_run1 = m_new1;

        // ---- O += P.V (split P, split V, 3 terms) ----
#pragma unroll
        for (int kc = 0; kc < 4; kc++) {
            const float* sa = s[2 * kc];
            const float* sc = s[2 * kc + 1];
            uint32_t ph[4], pl[4];
            ph[0] = pack_bf2(sa[0], sa[1]);
            ph[1] = pack_bf2(sa[2], sa[3]);
            ph[2] = pack_bf2(sc[0], sc[1]);
            ph[3] = pack_bf2(sc[2], sc[3]);
            pl[0] = pack_bf2(bf_res(sa[0]), bf_res(sa[1]));
            pl[1] = pack_bf2(bf_res(sa[2]), bf_res(sa[3]));
            pl[2] = pack_bf2(bf_res(sc[0]), bf_res(sc[1]));
            pl[3] = pack_bf2(bf_res(sc[2]), bf_res(sc[3]));

            const uint32_t rv = rowV + kc * 16;
#pragma unroll
            for (int dp = 0; dp < 4; dp++) {
                const uint32_t cV = ((2 * dp + hiV) ^ (rv & 7)) << 4;
                uint32_t vh4[4], vl4[4];
                LDSM_X4_T(vh4, svh + rv * 128 + cV);
                LDSM_X4_T(vl4, svl + rv * 128 + cV);
                MMA_BF16(o[dp * 2], ph, vh4[0], vh4[1]);
                MMA_BF16(o[dp * 2], pl, vh4[0], vh4[1]);
                MMA_BF16(o[dp * 2], ph, vl4[0], vl4[1]);
                MMA_BF16(o[dp * 2 + 1], ph, vh4[2], vh4[3]);
                MMA_BF16(o[dp * 2 + 1], pl, vh4[2], vh4[3]);
                MMA_BF16(o[dp * 2 + 1], ph, vl4[2], vl4[3]);
            }
        }
        __syncthreads();
    }
#undef ISSUE_KV

    // ---- normalize + store ----
    const float inv0 = 1.0f / l_run0;
    const float inv1 = 1.0f / l_run1;
    const int r0 = qbase + w * 16 + (lane >> 2);
#pragma unroll
    for (int nt = 0; nt < 8; nt++) {
        const int col = h * HD + nt * 8 + (lane & 3) * 2;
        *(float2*)(O + (size_t)(b * SEQ + r0) * DIM + col) =
            make_float2(o[nt][0] * inv0, o[nt][1] * inv0);
        *(float2*)(O + (size_t)(b * SEQ + r0 + 8) * DIM + col) =
            make_float2(o[nt][2] * inv1, o[nt][3] * inv1);
    }
}

// ---------------------------------------------------------------------------
// Launch
// ---------------------------------------------------------------------------
extern "C" void kernel_launch(void* const* d_in, const int* in_sizes, int n_in,
                              void* d_out, int out_size)
{
    const float* x    = (const float*)d_in[0];
    const int*   mask = (const int*)  d_in[1];
    const float* Wq   = (const float*)d_in[2];
    const float* bq   = (const float*)d_in[3];
    const float* Wk   = (const float*)d_in[4];
    const float* bk   = (const float*)d_in[5];
    const float* Wv   = (const float*)d_in[6];
    const float* bv   = (const float*)d_in[7];
    const float* Wf   = (const float*)d_in[8];
    const float* bf   = (const float*)d_in[9];
    float* out = (float*)d_out;

    float* ao;
    __nv_bfloat16 *xh, *xl, *wth, *wtl, *qh, *ql, *kh, *kl, *vh, *vl;
    cudaGetSymbolAddress((void**)&ao,  g_ao);
    cudaGetSymbolAddress((void**)&xh,  g_xh);
    cudaGetSymbolAddress((void**)&xl,  g_xl);
    cudaGetSymbolAddress((void**)&wth, g_wth);
    cudaGetSymbolAddress((void**)&wtl, g_wtl);
    cudaGetSymbolAddress((void**)&qh,  g_qh);
    cudaGetSymbolAddress((void**)&ql,  g_ql);
    cudaGetSymbolAddress((void**)&kh,  g_kh);
    cudaGetSymbolAddress((void**)&kl,  g_kl);
    cudaGetSymbolAddress((void**)&vh,  g_vh);
    cudaGetSymbolAddress((void**)&vl,  g_vl);

    static bool attr_set = false;
    if (!attr_set) {
        cudaFuncSetAttribute(gemm_mma_kernel,
                             cudaFuncAttributeMaxDynamicSharedMemorySize, GEMM_SMEM);
        cudaFuncSetAttribute(attn_mma_kernel,
                             cudaFuncAttributeMaxDynamicSharedMemorySize, ATTN_SMEM);
        attr_set = true;
    }

    const int n4 = MTOT * DIM / 4;
    const dim3 trg(32, 32), trb(32, 8);
    const dim3 ggrid(DIM / 128, MTOT / 128);

    split_kernel<<<(n4 + 255) / 256, 256>>>(x, xh, xl, n4);

    trsplit_kernel<<<trg, trb>>>(Wq, wth, wtl);
    gemm_mma_kernel<<<ggrid, 256, GEMM_SMEM>>>(xh, xl, wth, wtl, bq,
                                               nullptr, qh, ql, 1, 0.125f);
    trsplit_kernel<<<trg, trb>>>(Wk, wth, wtl);
    gemm_mma_kernel<<<ggrid, 256, GEMM_SMEM>>>(xh, xl, wth, wtl, bk,
                                               nullptr, kh, kl, 1, 1.0f);
    trsplit_kernel<<<trg, trb>>>(Wv, wth, wtl);
    gemm_mma_kernel<<<ggrid, 256, GEMM_SMEM>>>(xh, xl, wth, wtl, bv,
                                               nullptr, vh, vl, 1, 1.0f);

    attn_mma_kernel<<<dim3(SEQ / A_BM, NH, BSZ), 256, ATTN_SMEM>>>(
        qh, ql, kh, kl, vh, vl, mask, ao);

    split_kernel<<<(n4 + 255) / 256, 256>>>(ao, xh, xl, n4);
    trsplit_kernel<<<trg, trb>>>(Wf, wth, wtl);
    gemm_mma_kernel<<<ggrid, 256, GEMM_SMEM>>>(xh, xl, wth, wtl, bf,
                                               out, nullptr, nullptr, 0, 1.0f);
}

// round 5
// speedup vs baseline: 5.7230x; 1.5576x over previous
#include <cuda_runtime.h>
#include <cuda_bf16.h>
#include <stdint.h>
#include <math.h>

// Problem constants
#define BSZ   4
#define SEQ   2048
#define DIM   1024
#define NH    16
#define HD    64
#define MTOT  (BSZ * SEQ)          // 8192

// ---------------------------------------------------------------------------
// Scratch (device globals: allocation-guard safe)
// ---------------------------------------------------------------------------
__device__ float g_ao[(size_t)MTOT * DIM];
__device__ __nv_bfloat16 g_xh [(size_t)MTOT * DIM];
__device__ __nv_bfloat16 g_xl [(size_t)MTOT * DIM];
__device__ __nv_bfloat16 g_xch[(size_t)MTOT * DIM];   // compacted (per batch)
__device__ __nv_bfloat16 g_xcl[(size_t)MTOT * DIM];
__device__ __nv_bfloat16 g_wth[(size_t)DIM * DIM];
__device__ __nv_bfloat16 g_wtl[(size_t)DIM * DIM];
__device__ __nv_bfloat16 g_qh [(size_t)MTOT * DIM];
__device__ __nv_bfloat16 g_ql [(size_t)MTOT * DIM];
__device__ __nv_bfloat16 g_kh [(size_t)MTOT * DIM];
__device__ __nv_bfloat16 g_kl [(size_t)MTOT * DIM];
__device__ __nv_bfloat16 g_vh [(size_t)MTOT * DIM];
__device__ __nv_bfloat16 g_vl [(size_t)MTOT * DIM];
__device__ int g_gidx[MTOT];       // per-batch gather indices
__device__ int g_cnts[BSZ * 4];    // {cnt, pad64, pad128, _} per batch
__device__ int g_mskc[MTOT];       // compacted mask (0 keep, 1 pad)

// ---------------------------------------------------------------------------
// PTX helpers — portable sm_80+ only (harness targets plain sm_100)
// ---------------------------------------------------------------------------
__device__ __forceinline__ uint32_t smem_u32(const void* p) {
    uint32_t a;
    asm("{ .reg .u64 t; cvta.to.shared.u64 t, %1; cvt.u32.u64 %0, t; }"
        : "=r"(a) : "l"(p));
    return a;
}

#define CP_ASYNC16(dst, src) \
    asm volatile("cp.async.cg.shared.global [%0], [%1], 16;" \
                 :: "r"(dst), "l"(src))
#define CP_COMMIT() asm volatile("cp.async.commit_group;" ::: "memory")
#define CP_WAIT(N)  asm volatile("cp.async.wait_group %0;" :: "n"(N) : "memory")

#define LDSM_X4(R, addr) \
    asm volatile("ldmatrix.sync.aligned.m8n8.x4.shared.b16 {%0,%1,%2,%3}, [%4];" \
                 : "=r"((R)[0]), "=r"((R)[1]), "=r"((R)[2]), "=r"((R)[3]) \
                 : "r"(addr))
#define LDSM_X4_T(R, addr) \
    asm volatile("ldmatrix.sync.aligned.m8n8.x4.trans.shared.b16 {%0,%1,%2,%3}, [%4];" \
                 : "=r"((R)[0]), "=r"((R)[1]), "=r"((R)[2]), "=r"((R)[3]) \
                 : "r"(addr))

#define MMA_BF16(D, A, B0, B1) \
    asm volatile("mma.sync.aligned.m16n8k16.row.col.f32.bf16.bf16.f32 " \
                 "{%0,%1,%2,%3}, {%4,%5,%6,%7}, {%8,%9}, {%0,%1,%2,%3};" \
                 : "+f"((D)[0]), "+f"((D)[1]), "+f"((D)[2]), "+f"((D)[3]) \
                 : "r"((A)[0]), "r"((A)[1]), "r"((A)[2]), "r"((A)[3]), \
                   "r"(B0), "r"(B1))

__device__ __forceinline__ uint32_t pack_bf2(float lo, float hi) {
    __nv_bfloat162 t(__float2bfloat16(lo), __float2bfloat16(hi));
    return *(uint32_t*)&t;
}
__device__ __forceinline__ float bf_res(float f) {
    return f - __bfloat162float(__float2bfloat16(f));
}

// ---------------------------------------------------------------------------
// split fp32 -> (hi, lo) bf16
// ---------------------------------------------------------------------------
__global__ __launch_bounds__(256) void split_kernel(
    const float* __restrict__ src, __nv_bfloat16* __restrict__ hi,
    __nv_bfloat16* __restrict__ lo, int n4)
{
    int i = blockIdx.x * 256 + threadIdx.x;
    if (i >= n4) return;
    float4 v = ((const float4*)src)[i];
    __nv_bfloat16 h0 = __float2bfloat16(v.x), h1 = __float2bfloat16(v.y);
    __nv_bfloat16 h2 = __float2bfloat16(v.z), h3 = __float2bfloat16(v.w);
    __nv_bfloat16 l0 = __float2bfloat16(v.x - __bfloat162float(h0));
    __nv_bfloat16 l1 = __float2bfloat16(v.y - __bfloat162float(h1));
    __nv_bfloat16 l2 = __float2bfloat16(v.z - __bfloat162float(h2));
    __nv_bfloat16 l3 = __float2bfloat16(v.w - __bfloat162float(h3));
    ((__nv_bfloat162*)hi)[2 * i]     = __nv_bfloat162(h0, h1);
    ((__nv_bfloat162*)hi)[2 * i + 1] = __nv_bfloat162(h2, h3);
    ((__nv_bfloat162*)lo)[2 * i]     = __nv_bfloat162(l0, l1);
    ((__nv_bfloat162*)lo)[2 * i + 1] = __nv_bfloat162(l2, l3);
}

// ---------------------------------------------------------------------------
// per-batch scan over key mask: gather indices, counts, compacted mask
// grid = BSZ blocks of 1024 threads (2 positions per thread)
// ---------------------------------------------------------------------------
__global__ __launch_bounds__(1024) void mask_scan_kernel(
    const int* __restrict__ mask, int* __restrict__ gidx,
    int* __restrict__ cnts, int* __restrict__ mskc)
{
    __shared__ int sc[1024];
    const int b = blockIdx.x, t = threadIdx.x;
    const int base = b * SEQ;
    const int k0 = (mask[base + 2 * t]     == 0);
    const int k1 = (mask[base + 2 * t + 1] == 0);
    sc[t] = k0 + k1;
    __syncthreads();
#pragma unroll
    for (int off = 1; off < 1024; off <<= 1) {
        int v = sc[t];
        int u = (t >= off) ? sc[t - off] : 0;
        __syncthreads();
        sc[t] = v + u;
        __syncthreads();
    }
    const int incl = sc[t];
    const int pbase = incl - (k0 + k1);
    if (k0) gidx[base + pbase]      = 2 * t;
    if (k1) gidx[base + pbase + k0] = 2 * t + 1;
    const int tot = sc[1023];
    if (t == 0) {
        cnts[b * 4 + 0] = tot;
        cnts[b * 4 + 1] = (tot + 63)  & ~63;
        cnts[b * 4 + 2] = (tot + 127) & ~127;
    }
    mskc[base + 2 * t]     = (2 * t     < tot) ? 0 : 1;
    mskc[base + 2 * t + 1] = (2 * t + 1 < tot) ? 0 : 1;
}

// ---------------------------------------------------------------------------
// gather compacted x rows (zero rows in [cnt, pad128))
// grid = (SEQ, BSZ), 256 threads: 128 copy hi chunks, 128 copy lo chunks
// ---------------------------------------------------------------------------
__global__ __launch_bounds__(256) void gather_kernel(
    const __nv_bfloat16* __restrict__ xh, const __nv_bfloat16* __restrict__ xl,
    __nv_bfloat16* __restrict__ xch, __nv_bfloat16* __restrict__ xcl,
    const int* __restrict__ gidx, const int* __restrict__ cnts)
{
    const int j = blockIdx.x, b = blockIdx.y;
    const int tot = cnts[b * 4], pad128 = cnts[b * 4 + 2];
    if (j >= pad128) return;
    const int half = threadIdx.x >> 7;      // 0 = hi, 1 = lo
    const int ch   = threadIdx.x & 127;     // 16B chunk (128 x 16B = 2KB row)
    uint4 v = make_uint4(0, 0, 0, 0);
    if (j < tot) {
        const int src = gidx[b * SEQ + j];
        const __nv_bfloat16* s = (half ? xl : xh) + (size_t)(b * SEQ + src) * DIM;
        v = ((const uint4*)s)[ch];
    }
    __nv_bfloat16* d = (half ? xcl : xch) + (size_t)(b * SEQ + j) * DIM;
    ((uint4*)d)[ch] = v;
}

// ---------------------------------------------------------------------------
// transpose + split: Th[n][k] = bf16_hi(W[k][n]), Tl likewise
// ---------------------------------------------------------------------------
__global__ __launch_bounds__(256) void trsplit_kernel(
    const float* __restrict__ W, __nv_bfloat16* __restrict__ Th,
    __nv_bfloat16* __restrict__ Tl)
{
    __shared__ float t[32][33];
    int bx = blockIdx.x * 32, by = blockIdx.y * 32;
    int tx = threadIdx.x, ty = threadIdx.y;   // (32, 8)
#pragma unroll
    for (int j = 0; j < 4; j++)
        t[ty + j * 8][tx] = W[(size_t)(by + ty + j * 8) * DIM + bx + tx];
    __syncthreads();
#pragma unroll
    for (int j = 0; j < 4; j++) {
        float v = t[tx][ty + j * 8];
        __nv_bfloat16 h = __float2bfloat16(v);
        __nv_bfloat16 l = __float2bfloat16(v - __bfloat162float(h));
        size_t o = (size_t)(bx + ty + j * 8) * DIM + by + tx;
        Th[o] = h;
        Tl[o] = l;
    }
}

// ---------------------------------------------------------------------------
// mma.sync split-bf16 GEMM. mode 0: fp32 out. mode 1: (hi,lo) bf16 of
// scale*(acc+bias). Optional per-batch row limit (device) for early exit.
// ---------------------------------------------------------------------------
#define GT_TILE   16384
#define GT_STAGE  (4 * GT_TILE)     // 64 KB
#define GEMM_SMEM (2 * GT_STAGE)    // 128 KB

__global__ __launch_bounds__(256, 1) void gemm_mma_kernel(
    const __nv_bfloat16* __restrict__ Ahp, const __nv_bfloat16* __restrict__ Alp,
    const __nv_bfloat16* __restrict__ Bhp, const __nv_bfloat16* __restrict__ Blp,
    const float* __restrict__ bias, float* __restrict__ C,
    __nv_bfloat16* __restrict__ Chi, __nv_bfloat16* __restrict__ Clo,
    int mode, float scale, const int* __restrict__ rowlim)
{
    const int rbase = blockIdx.y * 128;
    if (rowlim && (rbase & (SEQ - 1)) >= rowlim[(rbase / SEQ) * 4 + 2]) return;

    extern __shared__ char smem[];
    const uint32_t sb = smem_u32(smem);
    const int tid  = threadIdx.x;
    const int lane = tid & 31;
    const int warp = tid >> 5;
    const int wm   = warp >> 2;
    const int wn   = warp & 3;
    const int cbase = blockIdx.x * 128;

    const int ldrow = tid >> 3;
    const int ldc8  = tid & 7;
    const __nv_bfloat16* srcs[4] = {Ahp, Alp, Bhp, Blp};

#define ISSUE_STAGE(KB, BUF)                                                     \
    do {                                                                         \
        uint32_t _sbase = sb + (BUF) * GT_STAGE;                                 \
        _Pragma("unroll")                                                        \
        for (int t4 = 0; t4 < 4; t4++) {                                         \
            const __nv_bfloat16* _S = srcs[t4];                                  \
            int _rb = (t4 < 2) ? rbase : cbase;                                  \
            _Pragma("unroll")                                                    \
            for (int it = 0; it < 4; it++) {                                     \
                int _row = ldrow + it * 32;                                      \
                uint32_t _dst = _sbase + t4 * GT_TILE + _row * 128               \
                              + ((ldc8 ^ (_row & 7)) << 4);                      \
                const __nv_bfloat16* _src = _S                                   \
                    + (size_t)(_rb + _row) * DIM + (KB) + ldc8 * 8;              \
                CP_ASYNC16(_dst, _src);                                          \
            }                                                                    \
        }                                                                        \
        CP_COMMIT();                                                             \
    } while (0)

    const uint32_t rA   = wm * 64 + (lane & 7) + ((lane >> 3) & 1) * 8;
    const uint32_t hiA  = lane >> 4;
    const uint32_t xorA = rA & 7;
    const uint32_t rB   = wn * 32 + (lane & 7) + (lane >> 4) * 8;
    const uint32_t hiB  = (lane >> 3) & 1;
    const uint32_t xorB = rB & 7;

    float acc[4][4][4];
#pragma unroll
    for (int i = 0; i < 4; i++)
#pragma unroll
        for (int j = 0; j < 4; j++)
#pragma unroll
            for (int r = 0; r < 4; r++) acc[i][j][r] = 0.f;

    ISSUE_STAGE(0, 0);

    const int NK = DIM / 64;
    for (int kc = 0; kc < NK; kc++) {
        if (kc + 1 < NK) {
            ISSUE_STAGE((kc + 1) * 64, (kc + 1) & 1);
            CP_WAIT(1);
        } else {
            CP_WAIT(0);
        }
        __syncthreads();

        const uint32_t st = sb + (kc & 1) * GT_STAGE;
        const uint32_t sAh = st;
        const uint32_t sAl = st + GT_TILE;
        const uint32_t sBh = st + 2 * GT_TILE;
        const uint32_t sBl = st + 3 * GT_TILE;

#pragma unroll
        for (int ks = 0; ks < 4; ks++) {
            uint32_t ah[4][4], al[4][4], bh[2][4], bl[2][4];
            const uint32_t cA = ((2 * ks + hiA) ^ xorA) << 4;
            const uint32_t cB = ((2 * ks + hiB) ^ xorB) << 4;
#pragma unroll
            for (int mt = 0; mt < 4; mt++) {
                uint32_t ro = (rA + mt * 16) * 128;
                LDSM_X4(ah[mt], sAh + ro + cA);
                LDSM_X4(al[mt], sAl + ro + cA);
            }
#pragma unroll
            for (int nb = 0; nb < 2; nb++) {
                uint32_t ro = (rB + nb * 16) * 128;
                LDSM_X4(bh[nb], sBh + ro + cB);
                LDSM_X4(bl[nb], sBl + ro + cB);
            }
#pragma unroll
            for (int mt = 0; mt < 4; mt++)
#pragma unroll
                for (int nt = 0; nt < 4; nt++) {
                    const int nb = nt >> 1, p = (nt & 1) * 2;
                    MMA_BF16(acc[mt][nt], ah[mt], bh[nb][p], bh[nb][p + 1]);
                    MMA_BF16(acc[mt][nt], ah[mt], bl[nb][p], bl[nb][p + 1]);
                    MMA_BF16(acc[mt][nt], al[mt], bh[nb][p], bh[nb][p + 1]);
                }
        }
        __syncthreads();
    }
#undef ISSUE_STAGE

#pragma unroll
    for (int mt = 0; mt < 4; mt++) {
        const int row0 = rbase + wm * 64 + mt * 16 + (lane >> 2);
#pragma unroll
        for (int nt = 0; nt < 4; nt++) {
            const int col = cbase + wn * 32 + nt * 8 + (lane & 3) * 2;
            const float b0 = bias[col], b1 = bias[col + 1];
            float v00 = acc[mt][nt][0] + b0, v01 = acc[mt][nt][1] + b1;
            float v10 = acc[mt][nt][2] + b0, v11 = acc[mt][nt][3] + b1;
            if (mode == 0) {
                *(float2*)(C + (size_t)row0 * DIM + col)       = make_float2(v00, v01);
                *(float2*)(C + (size_t)(row0 + 8) * DIM + col) = make_float2(v10, v11);
            } else {
                v00 *= scale; v01 *= scale; v10 *= scale; v11 *= scale;
                __nv_bfloat16 h00 = __float2bfloat16(v00), h01 = __float2bfloat16(v01);
                __nv_bfloat16 h10 = __float2bfloat16(v10), h11 = __float2bfloat16(v11);
                *(__nv_bfloat162*)(Chi + (size_t)row0 * DIM + col) = __nv_bfloat162(h00, h01);
                *(__nv_bfloat162*)(Chi + (size_t)(row0 + 8) * DIM + col) = __nv_bfloat162(h10, h11);
                *(__nv_bfloat162*)(Clo + (size_t)row0 * DIM + col) =
                    __nv_bfloat162(__float2bfloat16(v00 - __bfloat162float(h00)),
                                   __float2bfloat16(v01 - __bfloat162float(h01)));
                *(__nv_bfloat162*)(Clo + (size_t)(row0 + 8) * DIM + col) =
                    __nv_bfloat162(__float2bfloat16(v10 - __bfloat162float(h10)),
                                   __float2bfloat16(v11 - __bfloat162float(h11)));
            }
        }
    }
}

// ---------------------------------------------------------------------------
// Tensor-core flash attention over COMPACTED keys.
// CTA = (q-tile of 128, head, batch); tiles = pad64(b)/64 (device count).
// ---------------------------------------------------------------------------
#define A_BM 128
#define A_BN 64
#define AQ_H   0
#define AQ_L   16384
#define AKV    32768          // 2 stages x (Kh|Kl|Vh|Vl, 8KB each)
#define AMSK   98304
#define ATTN_SMEM (98304 + 512)

__global__ __launch_bounds__(256, 1) void attn_mma_kernel(
    const __nv_bfloat16* __restrict__ Qh, const __nv_bfloat16* __restrict__ Ql,
    const __nv_bfloat16* __restrict__ Kh, const __nv_bfloat16* __restrict__ Kl,
    const __nv_bfloat16* __restrict__ Vh, const __nv_bfloat16* __restrict__ Vl,
    const int* __restrict__ mskc, const int* __restrict__ cnts,
    float* __restrict__ O)
{
    extern __shared__ char smem[];
    const uint32_t sb = smem_u32(smem);
    const int tid  = threadIdx.x;
    const int lane = tid & 31;
    const int w    = tid >> 5;
    const int qbase = blockIdx.x * A_BM;
    const int h = blockIdx.y;
    const int b = blockIdx.z;
    const int nt_tiles = cnts[b * 4 + 1] >> 6;   // pad64/64

    const size_t hoff = (size_t)h * HD;
    const __nv_bfloat16* qhb = Qh + ((size_t)(b * SEQ + qbase)) * DIM + hoff;
    const __nv_bfloat16* qlb = Ql + ((size_t)(b * SEQ + qbase)) * DIM + hoff;
    const __nv_bfloat16* khb = Kh + ((size_t)b * SEQ) * DIM + hoff;
    const __nv_bfloat16* klb = Kl + ((size_t)b * SEQ) * DIM + hoff;
    const __nv_bfloat16* vhb = Vh + ((size_t)b * SEQ) * DIM + hoff;
    const __nv_bfloat16* vlb = Vl + ((size_t)b * SEQ) * DIM + hoff;

    const int ldrow = tid >> 3;
    const int ldc8  = tid & 7;

#pragma unroll
    for (int t = 0; t < 2; t++) {
        const __nv_bfloat16* src = t ? qlb : qhb;
        uint32_t dstb = sb + (t ? AQ_L : AQ_H);
#pragma unroll
        for (int it = 0; it < 4; it++) {
            int row = ldrow + it * 32;
            uint32_t dst = dstb + row * 128 + ((ldc8 ^ (row & 7)) << 4);
            CP_ASYNC16(dst, src + (size_t)row * DIM + ldc8 * 8);
        }
    }
    CP_COMMIT();

#define ISSUE_KV(KT, BUF)                                                        \
    do {                                                                         \
        int _kb = (KT) * A_BN;                                                   \
        uint32_t _db = sb + AKV + (BUF) * 32768;                                 \
        const __nv_bfloat16* _sp[4] = {khb, klb, vhb, vlb};                      \
        _Pragma("unroll")                                                        \
        for (int t4 = 0; t4 < 4; t4++) {                                         \
            _Pragma("unroll")                                                    \
            for (int it = 0; it < 2; it++) {                                     \
                int _row = ldrow + it * 32;                                      \
                uint32_t _dst = _db + t4 * 8192 + _row * 128                     \
                              + ((ldc8 ^ (_row & 7)) << 4);                      \
                CP_ASYNC16(_dst, _sp[t4] + (size_t)(_kb + _row) * DIM + ldc8 * 8); \
            }                                                                    \
        }                                                                        \
        CP_COMMIT();                                                             \
    } while (0)

    float* msks = (float*)(smem + AMSK);

    ISSUE_KV(0, 0);
    if (tid < 64)
        msks[tid] = mskc[b * SEQ + tid] ? 1.0f : 0.0f;
    CP_WAIT(0);
    __syncthreads();

    float o[8][4];
#pragma unroll
    for (int i = 0; i < 8; i++)
#pragma unroll
        for (int j = 0; j < 4; j++) o[i][j] = 0.f;
    float m_run0 = -3.0e38f, m_run1 = -3.0e38f;
    float l_run0 = 0.f, l_run1 = 0.f;

    const uint32_t rowA = w * 16 + (lane & 7) + ((lane >> 3) & 1) * 8;
    const uint32_t hiA  = lane >> 4;
    const uint32_t rowB = (lane & 7) + (lane >> 4) * 8;
    const uint32_t hiB  = (lane >> 3) & 1;
    const uint32_t rowV = (lane & 7) + ((lane >> 3) & 1) * 8;
    const uint32_t hiV  = lane >> 4;

    for (int kt = 0; kt < nt_tiles; kt++) {
        const int buf = kt & 1;
        if (kt + 1 < nt_tiles) {
            ISSUE_KV(kt + 1, 1 - buf);
            if (tid < 64)
                msks[(1 - buf) * 64 + tid] =
                    mskc[b * SEQ + (kt + 1) * A_BN + tid] ? 1.0f : 0.0f;
            CP_WAIT(1);
        } else {
            CP_WAIT(0);
        }
        __syncthreads();

        const uint32_t kvb = sb + AKV + buf * 32768;
        const uint32_t skh = kvb, skl = kvb + 8192;
        const uint32_t svh = kvb + 16384, svl = kvb + 24576;

        float s[8][4];
#pragma unroll
        for (int i = 0; i < 8; i++)
#pragma unroll
            for (int j = 0; j < 4; j++) s[i][j] = 0.f;

#pragma unroll
        for (int kc = 0; kc < 4; kc++) {
            uint32_t qh4[4], ql4[4];
            const uint32_t cA = ((2 * kc + hiA) ^ (rowA & 7)) << 4;
            LDSM_X4(qh4, sb + AQ_H + rowA * 128 + cA);
            LDSM_X4(ql4, sb + AQ_L + rowA * 128 + cA);
#pragma unroll
            for (int nt2 = 0; nt2 < 4; nt2++) {
                const uint32_t rb = rowB + nt2 * 16;
                const uint32_t cB = ((2 * kc + hiB) ^ (rb & 7)) << 4;
                uint32_t kh4[4], kl4[4];
                LDSM_X4(kh4, skh + rb * 128 + cB);
                LDSM_X4(kl4, skl + rb * 128 + cB);
                MMA_BF16(s[nt2 * 2], qh4, kh4[0], kh4[1]);
                MMA_BF16(s[nt2 * 2], qh4, kl4[0], kl4[1]);
                MMA_BF16(s[nt2 * 2], ql4, kh4[0], kh4[1]);
                MMA_BF16(s[nt2 * 2 + 1], qh4, kh4[2], kh4[3]);
                MMA_BF16(s[nt2 * 2 + 1], qh4, kl4[2], kl4[3]);
                MMA_BF16(s[nt2 * 2 + 1], ql4, kh4[2], kh4[3]);
            }
        }

        const float* mv = msks + buf * 64;
#pragma unroll
        for (int nt = 0; nt < 8; nt++) {
            int c0 = nt * 8 + (lane & 3) * 2;
            if (mv[c0]     > 0.5f) { s[nt][0] = -1.0e30f; s[nt][2] = -1.0e30f; }
            if (mv[c0 + 1] > 0.5f) { s[nt][1] = -1.0e30f; s[nt][3] = -1.0e30f; }
        }

        float mt0 = -3.0e38f, mt1 = -3.0e38f;
#pragma unroll
        for (int nt = 0; nt < 8; nt++) {
            mt0 = fmaxf(mt0, fmaxf(s[nt][0], s[nt][1]));
            mt1 = fmaxf(mt1, fmaxf(s[nt][2], s[nt][3]));
        }
        mt0 = fmaxf(mt0, __shfl_xor_sync(0xffffffffu, mt0, 1));
        mt0 = fmaxf(mt0, __shfl_xor_sync(0xffffffffu, mt0, 2));
        mt1 = fmaxf(mt1, __shfl_xor_sync(0xffffffffu, mt1, 1));
        mt1 = fmaxf(mt1, __shfl_xor_sync(0xffffffffu, mt1, 2));

        const float m_new0 = fmaxf(m_run0, mt0);
        const float m_new1 = fmaxf(m_run1, mt1);
        const float alpha0 = __expf(m_run0 - m_new0);
        const float alpha1 = __expf(m_run1 - m_new1);

#pragma unroll
        for (int nt = 0; nt < 8; nt++) {
            o[nt][0] *= alpha0; o[nt][1] *= alpha0;
            o[nt][2] *= alpha1; o[nt][3] *= alpha1;
        }

        float lt0 = 0.f, lt1 = 0.f;
#pragma unroll
        for (int nt = 0; nt < 8; nt++) {
            float p0 = __expf(s[nt][0] - m_new0);
            float p1 = __expf(s[nt][1] - m_new0);
            float p2 = __expf(s[nt][2] - m_new1);
            float p3 = __expf(s[nt][3] - m_new1);
            s[nt][0] = p0; s[nt][1] = p1; s[nt][2] = p2; s[nt][3] = p3;
            lt0 += p0 + p1; lt1 += p2 + p3;
        }
        lt0 += __shfl_xor_sync(0xffffffffu, lt0, 1);
        lt0 += __shfl_xor_sync(0xffffffffu, lt0, 2);
        lt1 += __shfl_xor_sync(0xffffffffu, lt1, 1);
        lt1 += __shfl_xor_sync(0xffffffffu, lt1, 2);

        l_run0 = l_run0 * alpha0 + lt0;
        l_run1 = l_run1 * alpha1 + lt1;
        m_run0 = m_new0;
        m_run1 = m_new1;

#pragma unroll
        for (int kc = 0; kc < 4; kc++) {
            const float* sa = s[2 * kc];
            const float* sc = s[2 * kc + 1];
            uint32_t ph[4], pl[4];
            ph[0] = pack_bf2(sa[0], sa[1]);
            ph[1] = pack_bf2(sa[2], sa[3]);
            ph[2] = pack_bf2(sc[0], sc[1]);
            ph[3] = pack_bf2(sc[2], sc[3]);
            pl[0] = pack_bf2(bf_res(sa[0]), bf_res(sa[1]));
            pl[1] = pack_bf2(bf_res(sa[2]), bf_res(sa[3]));
            pl[2] = pack_bf2(bf_res(sc[0]), bf_res(sc[1]));
            pl[3] = pack_bf2(bf_res(sc[2]), bf_res(sc[3]));

            const uint32_t rv = rowV + kc * 16;
#pragma unroll
            for (int dp = 0; dp < 4; dp++) {
                const uint32_t cV = ((2 * dp + hiV) ^ (rv & 7)) << 4;
                uint32_t vh4[4], vl4[4];
                LDSM_X4_T(vh4, svh + rv * 128 + cV);
                LDSM_X4_T(vl4, svl + rv * 128 + cV);
                MMA_BF16(o[dp * 2], ph, vh4[0], vh4[1]);
                MMA_BF16(o[dp * 2], pl, vh4[0], vh4[1]);
                MMA_BF16(o[dp * 2], ph, vl4[0], vl4[1]);
                MMA_BF16(o[dp * 2 + 1], ph, vh4[2], vh4[3]);
                MMA_BF16(o[dp * 2 + 1], pl, vh4[2], vh4[3]);
                MMA_BF16(o[dp * 2 + 1], ph, vl4[2], vl4[3]);
            }
        }
        __syncthreads();
    }
#undef ISSUE_KV

    const float inv0 = 1.0f / l_run0;
    const float inv1 = 1.0f / l_run1;
    const int r0 = qbase + w * 16 + (lane >> 2);
#pragma unroll
    for (int nt = 0; nt < 8; nt++) {
        const int col = h * HD + nt * 8 + (lane & 3) * 2;
        *(float2*)(O + (size_t)(b * SEQ + r0) * DIM + col) =
            make_float2(o[nt][0] * inv0, o[nt][1] * inv0);
        *(float2*)(O + (size_t)(b * SEQ + r0 + 8) * DIM + col) =
            make_float2(o[nt][2] * inv1, o[nt][3] * inv1);
    }
}

// ---------------------------------------------------------------------------
// Launch
// ---------------------------------------------------------------------------
extern "C" void kernel_launch(void* const* d_in, const int* in_sizes, int n_in,
                              void* d_out, int out_size)
{
    const float* x    = (const float*)d_in[0];
    const int*   mask = (const int*)  d_in[1];
    const float* Wq   = (const float*)d_in[2];
    const float* bq   = (const float*)d_in[3];
    const float* Wk   = (const float*)d_in[4];
    const float* bk   = (const float*)d_in[5];
    const float* Wv   = (const float*)d_in[6];
    const float* bv   = (const float*)d_in[7];
    const float* Wf   = (const float*)d_in[8];
    const float* bf   = (const float*)d_in[9];
    float* out = (float*)d_out;

    float* ao;
    __nv_bfloat16 *xh, *xl, *xch, *xcl, *wth, *wtl, *qh, *ql, *kh, *kl, *vh, *vl;
    int *gidx, *cnts, *mskc;
    cudaGetSymbolAddress((void**)&ao,  g_ao);
    cudaGetSymbolAddress((void**)&xh,  g_xh);
    cudaGetSymbolAddress((void**)&xl,  g_xl);
    cudaGetSymbolAddress((void**)&xch, g_xch);
    cudaGetSymbolAddress((void**)&xcl, g_xcl);
    cudaGetSymbolAddress((void**)&wth, g_wth);
    cudaGetSymbolAddress((void**)&wtl, g_wtl);
    cudaGetSymbolAddress((void**)&qh,  g_qh);
    cudaGetSymbolAddress((void**)&ql,  g_ql);
    cudaGetSymbolAddress((void**)&kh,  g_kh);
    cudaGetSymbolAddress((void**)&kl,  g_kl);
    cudaGetSymbolAddress((void**)&vh,  g_vh);
    cudaGetSymbolAddress((void**)&vl,  g_vl);
    cudaGetSymbolAddress((void**)&gidx, g_gidx);
    cudaGetSymbolAddress((void**)&cnts, g_cnts);
    cudaGetSymbolAddress((void**)&mskc, g_mskc);

    static bool attr_set = false;
    if (!attr_set) {
        cudaFuncSetAttribute(gemm_mma_kernel,
                             cudaFuncAttributeMaxDynamicSharedMemorySize, GEMM_SMEM);
        cudaFuncSetAttribute(attn_mma_kernel,
                             cudaFuncAttributeMaxDynamicSharedMemorySize, ATTN_SMEM);
        attr_set = true;
    }

    const int n4 = MTOT * DIM / 4;
    const dim3 trg(32, 32), trb(32, 8);
    const dim3 ggrid(DIM / 128, MTOT / 128);

    // split x, build compaction, gather compacted x
    split_kernel<<<(n4 + 255) / 256, 256>>>(x, xh, xl, n4);
    mask_scan_kernel<<<BSZ, 1024>>>(mask, gidx, cnts, mskc);
    gather_kernel<<<dim3(SEQ, BSZ), 256>>>(xh, xl, xch, xcl, gidx, cnts);

    // Q over all rows (scale 1/8 folded); K/V over compacted rows only
    trsplit_kernel<<<trg, trb>>>(Wq, wth, wtl);
    gemm_mma_kernel<<<ggrid, 256, GEMM_SMEM>>>(xh, xl, wth, wtl, bq,
                                               nullptr, qh, ql, 1, 0.125f, nullptr);
    trsplit_kernel<<<trg, trb>>>(Wk, wth, wtl);
    gemm_mma_kernel<<<ggrid, 256, GEMM_SMEM>>>(xch, xcl, wth, wtl, bk,
                                               nullptr, kh, kl, 1, 1.0f, cnts);
    trsplit_kernel<<<trg, trb>>>(Wv, wth, wtl);
    gemm_mma_kernel<<<ggrid, 256, GEMM_SMEM>>>(xch, xcl, wth, wtl, bv,
                                               nullptr, vh, vl, 1, 1.0f, cnts);

    attn_mma_kernel<<<dim3(SEQ / A_BM, NH, BSZ), 256, ATTN_SMEM>>>(
        qh, ql, kh, kl, vh, vl, mskc, cnts, ao);

    split_kernel<<<(n4 + 255) / 256, 256>>>(ao, xh, xl, n4);
    trsplit_kernel<<<trg, trb>>>(Wf, wth, wtl);
    gemm_mma_kernel<<<ggrid, 256, GEMM_SMEM>>>(xh, xl, wth, wtl, bf,
                                               out, nullptr, nullptr, 0, 1.0f, nullptr);
}

// round 7
// speedup vs baseline: 5.8036x; 1.0141x over previous
#include <cuda_runtime.h>
#include <cuda_bf16.h>
#include <stdint.h>
#include <math.h>

// Problem constants
#define BSZ   4
#define SEQ   2048
#define DIM   1024
#define NH    16
#define HD    64
#define MTOT  (BSZ * SEQ)          // 8192
#define LOG2E 1.4426950408889634f

// ---------------------------------------------------------------------------
// Scratch (device globals: allocation-guard safe)
// ---------------------------------------------------------------------------
__device__ __nv_bfloat16 g_xh [(size_t)MTOT * DIM];   // split x; later attn out
__device__ __nv_bfloat16 g_xl [(size_t)MTOT * DIM];
__device__ __nv_bfloat16 g_xch[(size_t)MTOT * DIM];   // compacted (per batch)
__device__ __nv_bfloat16 g_xcl[(size_t)MTOT * DIM];
__device__ __nv_bfloat16 g_wqh[(size_t)DIM * DIM];
__device__ __nv_bfloat16 g_wql[(size_t)DIM * DIM];
__device__ __nv_bfloat16 g_wkh[(size_t)DIM * DIM];
__device__ __nv_bfloat16 g_wkl[(size_t)DIM * DIM];
__device__ __nv_bfloat16 g_wvh[(size_t)DIM * DIM];
__device__ __nv_bfloat16 g_wvl[(size_t)DIM * DIM];
__device__ __nv_bfloat16 g_wfh[(size_t)DIM * DIM];
__device__ __nv_bfloat16 g_wfl[(size_t)DIM * DIM];
__device__ __nv_bfloat16 g_qh [(size_t)MTOT * DIM];
__device__ __nv_bfloat16 g_ql [(size_t)MTOT * DIM];
__device__ __nv_bfloat16 g_kh [(size_t)MTOT * DIM];
__device__ __nv_bfloat16 g_kl [(size_t)MTOT * DIM];
__device__ __nv_bfloat16 g_vh [(size_t)MTOT * DIM];
__device__ __nv_bfloat16 g_vl [(size_t)MTOT * DIM];
__device__ int g_gidx[MTOT];
__device__ int g_cnts[BSZ * 4];    // {cnt, pad64, pad128, _}
__device__ int g_mskc[MTOT];

// ---------------------------------------------------------------------------
// PTX helpers — portable sm_80+ only (harness targets plain sm_100)
// ---------------------------------------------------------------------------
__device__ __forceinline__ uint32_t smem_u32(const void* p) {
    uint32_t a;
    asm("{ .reg .u64 t; cvta.to.shared.u64 t, %1; cvt.u32.u64 %0, t; }"
        : "=r"(a) : "l"(p));
    return a;
}

#define CP_ASYNC16(dst, src) \
    asm volatile("cp.async.cg.shared.global [%0], [%1], 16;" \
                 :: "r"(dst), "l"(src))
#define CP_COMMIT() asm volatile("cp.async.commit_group;" ::: "memory")
#define CP_WAIT(N)  asm volatile("cp.async.wait_group %0;" :: "n"(N) : "memory")

#define LDSM_X4(R, addr) \
    asm volatile("ldmatrix.sync.aligned.m8n8.x4.shared.b16 {%0,%1,%2,%3}, [%4];" \
                 : "=r"((R)[0]), "=r"((R)[1]), "=r"((R)[2]), "=r"((R)[3]) \
                 : "r"(addr))
#define LDSM_X4_T(R, addr) \
    asm volatile("ldmatrix.sync.aligned.m8n8.x4.trans.shared.b16 {%0,%1,%2,%3}, [%4];" \
                 : "=r"((R)[0]), "=r"((R)[1]), "=r"((R)[2]), "=r"((R)[3]) \
                 : "r"(addr))

#define MMA_BF16(D, A, B0, B1) \
    asm volatile("mma.sync.aligned.m16n8k16.row.col.f32.bf16.bf16.f32 " \
                 "{%0,%1,%2,%3}, {%4,%5,%6,%7}, {%8,%9}, {%0,%1,%2,%3};" \
                 : "+f"((D)[0]), "+f"((D)[1]), "+f"((D)[2]), "+f"((D)[3]) \
                 : "r"((A)[0]), "r"((A)[1]), "r"((A)[2]), "r"((A)[3]), \
                   "r"(B0), "r"(B1))

__device__ __forceinline__ uint32_t pack_bf2(float lo, float hi) {
    __nv_bfloat162 t(__float2bfloat16(lo), __float2bfloat16(hi));
    return *(uint32_t*)&t;
}
__device__ __forceinline__ float bf_res(float f) {
    return f - __bfloat162float(__float2bfloat16(f));
}

// ---------------------------------------------------------------------------
// split fp32 -> (hi, lo) bf16
// ---------------------------------------------------------------------------
__global__ __launch_bounds__(256) void split_kernel(
    const float* __restrict__ src, __nv_bfloat16* __restrict__ hi,
    __nv_bfloat16* __restrict__ lo, int n4)
{
    int i = blockIdx.x * 256 + threadIdx.x;
    if (i >= n4) return;
    float4 v = ((const float4*)src)[i];
    __nv_bfloat16 h0 = __float2bfloat16(v.x), h1 = __float2bfloat16(v.y);
    __nv_bfloat16 h2 = __float2bfloat16(v.z), h3 = __float2bfloat16(v.w);
    __nv_bfloat16 l0 = __float2bfloat16(v.x - __bfloat162float(h0));
    __nv_bfloat16 l1 = __float2bfloat16(v.y - __bfloat162float(h1));
    __nv_bfloat16 l2 = __float2bfloat16(v.z - __bfloat162float(h2));
    __nv_bfloat16 l3 = __float2bfloat16(v.w - __bfloat162float(h3));
    ((__nv_bfloat162*)hi)[2 * i]     = __nv_bfloat162(h0, h1);
    ((__nv_bfloat162*)hi)[2 * i + 1] = __nv_bfloat162(h2, h3);
    ((__nv_bfloat162*)lo)[2 * i]     = __nv_bfloat162(l0, l1);
    ((__nv_bfloat162*)lo)[2 * i + 1] = __nv_bfloat162(l2, l3);
}

// ---------------------------------------------------------------------------
// per-batch scan over key mask: gather indices, counts, compacted mask
// ---------------------------------------------------------------------------
__global__ __launch_bounds__(1024) void mask_scan_kernel(
    const int* __restrict__ mask, int* __restrict__ gidx,
    int* __restrict__ cnts, int* __restrict__ mskc)
{
    __shared__ int sc[1024];
    const int b = blockIdx.x, t = threadIdx.x;
    const int base = b * SEQ;
    const int k0 = (mask[base + 2 * t]     == 0);
    const int k1 = (mask[base + 2 * t + 1] == 0);
    sc[t] = k0 + k1;
    __syncthreads();
#pragma unroll
    for (int off = 1; off < 1024; off <<= 1) {
        int v = sc[t];
        int u = (t >= off) ? sc[t - off] : 0;
        __syncthreads();
        sc[t] = v + u;
        __syncthreads();
    }
    const int incl = sc[t];
    const int pbase = incl - (k0 + k1);
    if (k0) gidx[base + pbase]      = 2 * t;
    if (k1) gidx[base + pbase + k0] = 2 * t + 1;
    const int tot = sc[1023];
    if (t == 0) {
        cnts[b * 4 + 0] = tot;
        cnts[b * 4 + 1] = (tot + 63)  & ~63;
        cnts[b * 4 + 2] = (tot + 127) & ~127;
    }
    mskc[base + 2 * t]     = (2 * t     < tot) ? 0 : 1;
    mskc[base + 2 * t + 1] = (2 * t + 1 < tot) ? 0 : 1;
}

// ---------------------------------------------------------------------------
// gather compacted x rows (zero rows in [cnt, pad128))
// ---------------------------------------------------------------------------
__global__ __launch_bounds__(256) void gather_kernel(
    const __nv_bfloat16* __restrict__ xh, const __nv_bfloat16* __restrict__ xl,
    __nv_bfloat16* __restrict__ xch, __nv_bfloat16* __restrict__ xcl,
    const int* __restrict__ gidx, const int* __restrict__ cnts)
{
    const int j = blockIdx.x, b = blockIdx.y;
    const int tot = cnts[b * 4], pad128 = cnts[b * 4 + 2];
    if (j >= pad128) return;
    const int half = threadIdx.x >> 7;
    const int ch   = threadIdx.x & 127;
    uint4 v = make_uint4(0, 0, 0, 0);
    if (j < tot) {
        const int src = gidx[b * SEQ + j];
        const __nv_bfloat16* s = (half ? xl : xh) + (size_t)(b * SEQ + src) * DIM;
        v = ((const uint4*)s)[ch];
    }
    __nv_bfloat16* d = (half ? xcl : xch) + (size_t)(b * SEQ + j) * DIM;
    ((uint4*)d)[ch] = v;
}

// ---------------------------------------------------------------------------
// transpose + split all 4 weights in one launch (blockIdx.z selects weight)
// ---------------------------------------------------------------------------
__global__ __launch_bounds__(256) void trsplit4_kernel(
    const float* __restrict__ W0, const float* __restrict__ W1,
    const float* __restrict__ W2, const float* __restrict__ W3,
    __nv_bfloat16* __restrict__ Th0, __nv_bfloat16* __restrict__ Tl0,
    __nv_bfloat16* __restrict__ Th1, __nv_bfloat16* __restrict__ Tl1,
    __nv_bfloat16* __restrict__ Th2, __nv_bfloat16* __restrict__ Tl2,
    __nv_bfloat16* __restrict__ Th3, __nv_bfloat16* __restrict__ Tl3)
{
    const float* W; __nv_bfloat16 *Th, *Tl;
    switch (blockIdx.z) {
        case 0:  W = W0; Th = Th0; Tl = Tl0; break;
        case 1:  W = W1; Th = Th1; Tl = Tl1; break;
        case 2:  W = W2; Th = Th2; Tl = Tl2; break;
        default: W = W3; Th = Th3; Tl = Tl3; break;
    }
    __shared__ float t[32][33];
    int bx = blockIdx.x * 32, by = blockIdx.y * 32;
    int tx = threadIdx.x, ty = threadIdx.y;   // (32, 8)
#pragma unroll
    for (int j = 0; j < 4; j++)
        t[ty + j * 8][tx] = W[(size_t)(by + ty + j * 8) * DIM + bx + tx];
    __syncthreads();
#pragma unroll
    for (int j = 0; j < 4; j++) {
        float v = t[tx][ty + j * 8];
        __nv_bfloat16 h = __float2bfloat16(v);
        __nv_bfloat16 l = __float2bfloat16(v - __bfloat162float(h));
        size_t o = (size_t)(bx + ty + j * 8) * DIM + by + tx;
        Th[o] = h;
        Tl[o] = l;
    }
}

// ---------------------------------------------------------------------------
// mma.sync split-bf16 GEMM. mode 0: fp32 out. mode 1: (hi,lo) bf16 of
// scale*(acc+bias). Optional per-batch row limit (device) for early exit.
// ---------------------------------------------------------------------------
#define GT_TILE   16384
#define GT_STAGE  (4 * GT_TILE)     // 64 KB
#define GEMM_SMEM (2 * GT_STAGE)    // 128 KB

__global__ __launch_bounds__(256, 1) void gemm_mma_kernel(
    const __nv_bfloat16* __restrict__ Ahp, const __nv_bfloat16* __restrict__ Alp,
    const __nv_bfloat16* __restrict__ Bhp, const __nv_bfloat16* __restrict__ Blp,
    const float* __restrict__ bias, float* __restrict__ C,
    __nv_bfloat16* __restrict__ Chi, __nv_bfloat16* __restrict__ Clo,
    int mode, float scale, const int* __restrict__ rowlim)
{
    const int rbase = blockIdx.y * 128;
    if (rowlim && (rbase & (SEQ - 1)) >= rowlim[(rbase / SEQ) * 4 + 2]) return;

    extern __shared__ char smem[];
    const uint32_t sb = smem_u32(smem);
    const int tid  = threadIdx.x;
    const int lane = tid & 31;
    const int warp = tid >> 5;
    const int wm   = warp >> 2;
    const int wn   = warp & 3;
    const int cbase = blockIdx.x * 128;

    const int ldrow = tid >> 3;
    const int ldc8  = tid & 7;
    const __nv_bfloat16* srcs[4] = {Ahp, Alp, Bhp, Blp};

#define ISSUE_STAGE(KB, BUF)                                                     \
    do {                                                                         \
        uint32_t _sbase = sb + (BUF) * GT_STAGE;                                 \
        _Pragma("unroll")                                                        \
        for (int t4 = 0; t4 < 4; t4++) {                                         \
            const __nv_bfloat16* _S = srcs[t4];                                  \
            int _rb = (t4 < 2) ? rbase : cbase;                                  \
            _Pragma("unroll")                                                    \
            for (int it = 0; it < 4; it++) {                                     \
                int _row = ldrow + it * 32;                                      \
                uint32_t _dst = _sbase + t4 * GT_TILE + _row * 128               \
                              + ((ldc8 ^ (_row & 7)) << 4);                      \
                const __nv_bfloat16* _src = _S                                   \
                    + (size_t)(_rb + _row) * DIM + (KB) + ldc8 * 8;              \
                CP_ASYNC16(_dst, _src);                                          \
            }                                                                    \
        }                                                                        \
        CP_COMMIT();                                                             \
    } while (0)

    const uint32_t rA   = wm * 64 + (lane & 7) + ((lane >> 3) & 1) * 8;
    const uint32_t hiA  = lane >> 4;
    const uint32_t xorA = rA & 7;
    const uint32_t rB   = wn * 32 + (lane & 7) + (lane >> 4) * 8;
    const uint32_t hiB  = (lane >> 3) & 1;
    const uint32_t xorB = rB & 7;

    float acc[4][4][4];
#pragma unroll
    for (int i = 0; i < 4; i++)
#pragma unroll
        for (int j = 0; j < 4; j++)
#pragma unroll
            for (int r = 0; r < 4; r++) acc[i][j][r] = 0.f;

    ISSUE_STAGE(0, 0);

    const int NK = DIM / 64;
    for (int kc = 0; kc < NK; kc++) {
        if (kc + 1 < NK) {
            ISSUE_STAGE((kc + 1) * 64, (kc + 1) & 1);
            CP_WAIT(1);
        } else {
            CP_WAIT(0);
        }
        __syncthreads();

        const uint32_t st = sb + (kc & 1) * GT_STAGE;
        const uint32_t sAh = st;
        const uint32_t sAl = st + GT_TILE;
        const uint32_t sBh = st + 2 * GT_TILE;
        const uint32_t sBl = st + 3 * GT_TILE;

#pragma unroll
        for (int ks = 0; ks < 4; ks++) {
            uint32_t ah[4][4], al[4][4], bh[2][4], bl[2][4];
            const uint32_t cA = ((2 * ks + hiA) ^ xorA) << 4;
            const uint32_t cB = ((2 * ks + hiB) ^ xorB) << 4;
#pragma unroll
            for (int mt = 0; mt < 4; mt++) {
                uint32_t ro = (rA + mt * 16) * 128;
                LDSM_X4(ah[mt], sAh + ro + cA);
                LDSM_X4(al[mt], sAl + ro + cA);
            }
#pragma unroll
            for (int nb = 0; nb < 2; nb++) {
                uint32_t ro = (rB + nb * 16) * 128;
                LDSM_X4(bh[nb], sBh + ro + cB);
                LDSM_X4(bl[nb], sBl + ro + cB);
            }
#pragma unroll
            for (int mt = 0; mt < 4; mt++)
#pragma unroll
                for (int nt = 0; nt < 4; nt++) {
                    const int nb = nt >> 1, p = (nt & 1) * 2;
                    MMA_BF16(acc[mt][nt], ah[mt], bh[nb][p], bh[nb][p + 1]);
                    MMA_BF16(acc[mt][nt], ah[mt], bl[nb][p], bl[nb][p + 1]);
                    MMA_BF16(acc[mt][nt], al[mt], bh[nb][p], bh[nb][p + 1]);
                }
        }
        __syncthreads();
    }
#undef ISSUE_STAGE

#pragma unroll
    for (int mt = 0; mt < 4; mt++) {
        const int row0 = rbase + wm * 64 + mt * 16 + (lane >> 2);
#pragma unroll
        for (int nt = 0; nt < 4; nt++) {
            const int col = cbase + wn * 32 + nt * 8 + (lane & 3) * 2;
            const float b0 = bias[col], b1 = bias[col + 1];
            float v00 = acc[mt][nt][0] + b0, v01 = acc[mt][nt][1] + b1;
            float v10 = acc[mt][nt][2] + b0, v11 = acc[mt][nt][3] + b1;
            if (mode == 0) {
                *(float2*)(C + (size_t)row0 * DIM + col)       = make_float2(v00, v01);
                *(float2*)(C + (size_t)(row0 + 8) * DIM + col) = make_float2(v10, v11);
            } else {
                v00 *= scale; v01 *= scale; v10 *= scale; v11 *= scale;
                __nv_bfloat16 h00 = __float2bfloat16(v00), h01 = __float2bfloat16(v01);
                __nv_bfloat16 h10 = __float2bfloat16(v10), h11 = __float2bfloat16(v11);
                *(__nv_bfloat162*)(Chi + (size_t)row0 * DIM + col) = __nv_bfloat162(h00, h01);
                *(__nv_bfloat162*)(Chi + (size_t)(row0 + 8) * DIM + col) = __nv_bfloat162(h10, h11);
                *(__nv_bfloat162*)(Clo + (size_t)row0 * DIM + col) =
                    __nv_bfloat162(__float2bfloat16(v00 - __bfloat162float(h00)),
                                   __float2bfloat16(v01 - __bfloat162float(h01)));
                *(__nv_bfloat162*)(Clo + (size_t)(row0 + 8) * DIM + col) =
                    __nv_bfloat162(__float2bfloat16(v10 - __bfloat162float(h10)),
                                   __float2bfloat16(v11 - __bfloat162float(h11)));
            }
        }
    }
}

// ---------------------------------------------------------------------------
// Tensor-core flash attention over COMPACTED keys, base-2 softmax
// (Q pre-scaled by 0.125*log2e). Output written as (hi,lo) bf16.
// ---------------------------------------------------------------------------
#define A_BM 128
#define A_BN 64
#define AQ_H   0
#define AQ_L   16384
#define AKV    32768          // 2 stages x (Kh|Kl|Vh|Vl, 8KB each)
#define AMSK   98304
#define ATTN_SMEM (98304 + 512)

__global__ __launch_bounds__(256, 1) void attn_mma_kernel(
    const __nv_bfloat16* __restrict__ Qh, const __nv_bfloat16* __restrict__ Ql,
    const __nv_bfloat16* __restrict__ Kh, const __nv_bfloat16* __restrict__ Kl,
    const __nv_bfloat16* __restrict__ Vh, const __nv_bfloat16* __restrict__ Vl,
    const int* __restrict__ mskc, const int* __restrict__ cnts,
    __nv_bfloat16* __restrict__ AOh, __nv_bfloat16* __restrict__ AOl)
{
    extern __shared__ char smem[];
    const uint32_t sb = smem_u32(smem);
    const int tid  = threadIdx.x;
    const int lane = tid & 31;
    const int w    = tid >> 5;
    const int qbase = blockIdx.x * A_BM;
    const int h = blockIdx.y;
    const int b = blockIdx.z;
    const int nt_tiles = cnts[b * 4 + 1] >> 6;

    const size_t hoff = (size_t)h * HD;
    const __nv_bfloat16* qhb = Qh + ((size_t)(b * SEQ + qbase)) * DIM + hoff;
    const __nv_bfloat16* qlb = Ql + ((size_t)(b * SEQ + qbase)) * DIM + hoff;
    const __nv_bfloat16* khb = Kh + ((size_t)b * SEQ) * DIM + hoff;
    const __nv_bfloat16* klb = Kl + ((size_t)b * SEQ) * DIM + hoff;
    const __nv_bfloat16* vhb = Vh + ((size_t)b * SEQ) * DIM + hoff;
    const __nv_bfloat16* vlb = Vl + ((size_t)b * SEQ) * DIM + hoff;

    const int ldrow = tid >> 3;
    const int ldc8  = tid & 7;

#pragma unroll
    for (int t = 0; t < 2; t++) {
        const __nv_bfloat16* src = t ? qlb : qhb;
        uint32_t dstb = sb + (t ? AQ_L : AQ_H);
#pragma unroll
        for (int it = 0; it < 4; it++) {
            int row = ldrow + it * 32;
            uint32_t dst = dstb + row * 128 + ((ldc8 ^ (row & 7)) << 4);
            CP_ASYNC16(dst, src + (size_t)row * DIM + ldc8 * 8);
        }
    }
    CP_COMMIT();

#define ISSUE_KV(KT, BUF)                                                        \
    do {                                                                         \
        int _kb = (KT) * A_BN;                                                   \
        uint32_t _db = sb + AKV + (BUF) * 32768;                                 \
        const __nv_bfloat16* _sp[4] = {khb, klb, vhb, vlb};                      \
        _Pragma("unroll")                                                        \
        for (int t4 = 0; t4 < 4; t4++) {                                         \
            _Pragma("unroll")                                                    \
            for (int it = 0; it < 2; it++) {                                     \
                int _row = ldrow + it * 32;                                      \
                uint32_t _dst = _db + t4 * 8192 + _row * 128                     \
                              + ((ldc8 ^ (_row & 7)) << 4);                      \
                CP_ASYNC16(_dst, _sp[t4] + (size_t)(_kb + _row) * DIM + ldc8 * 8); \
            }                                                                    \
        }                                                                        \
        CP_COMMIT();                                                             \
    } while (0)

    float* msks = (float*)(smem + AMSK);

    ISSUE_KV(0, 0);
    if (tid < 64)
        msks[tid] = mskc[b * SEQ + tid] ? 1.0f : 0.0f;
    CP_WAIT(0);
    __syncthreads();

    float o[8][4];
#pragma unroll
    for (int i = 0; i < 8; i++)
#pragma unroll
        for (int j = 0; j < 4; j++) o[i][j] = 0.f;
    float m_run0 = -3.0e38f, m_run1 = -3.0e38f;
    float l_run0 = 0.f, l_run1 = 0.f;

    const uint32_t rowA = w * 16 + (lane & 7) + ((lane >> 3) & 1) * 8;
    const uint32_t hiA  = lane >> 4;
    const uint32_t rowB = (lane & 7) + (lane >> 4) * 8;
    const uint32_t hiB  = (lane >> 3) & 1;
    const uint32_t rowV = (lane & 7) + ((lane >> 3) & 1) * 8;
    const uint32_t hiV  = lane >> 4;

    for (int kt = 0; kt < nt_tiles; kt++) {
        const int buf = kt & 1;
        if (kt + 1 < nt_tiles) {
            ISSUE_KV(kt + 1, 1 - buf);
            if (tid < 64)
                msks[(1 - buf) * 64 + tid] =
                    mskc[b * SEQ + (kt + 1) * A_BN + tid] ? 1.0f : 0.0f;
            CP_WAIT(1);
        } else {
            CP_WAIT(0);
        }
        __syncthreads();

        const uint32_t kvb = sb + AKV + buf * 32768;
        const uint32_t skh = kvb, skl = kvb + 8192;
        const uint32_t svh = kvb + 16384, svl = kvb + 24576;

        float s[8][4];
#pragma unroll
        for (int i = 0; i < 8; i++)
#pragma unroll
            for (int j = 0; j < 4; j++) s[i][j] = 0.f;

#pragma unroll
        for (int kc = 0; kc < 4; kc++) {
            uint32_t qh4[4], ql4[4];
            const uint32_t cA = ((2 * kc + hiA) ^ (rowA & 7)) << 4;
            LDSM_X4(qh4, sb + AQ_H + rowA * 128 + cA);
            LDSM_X4(ql4, sb + AQ_L + rowA * 128 + cA);
#pragma unroll
            for (int nt2 = 0; nt2 < 4; nt2++) {
                const uint32_t rb = rowB + nt2 * 16;
                const uint32_t cB = ((2 * kc + hiB) ^ (rb & 7)) << 4;
                uint32_t kh4[4], kl4[4];
                LDSM_X4(kh4, skh + rb * 128 + cB);
                LDSM_X4(kl4, skl + rb * 128 + cB);
                MMA_BF16(s[nt2 * 2], qh4, kh4[0], kh4[1]);
                MMA_BF16(s[nt2 * 2], qh4, kl4[0], kl4[1]);
                MMA_BF16(s[nt2 * 2], ql4, kh4[0], kh4[1]);
                MMA_BF16(s[nt2 * 2 + 1], qh4, kh4[2], kh4[3]);
                MMA_BF16(s[nt2 * 2 + 1], qh4, kl4[2], kl4[3]);
                MMA_BF16(s[nt2 * 2 + 1], ql4, kh4[2], kh4[3]);
            }
        }

        const float* mv = msks + buf * 64;
#pragma unroll
        for (int nt = 0; nt < 8; nt++) {
            int c0 = nt * 8 + (lane & 3) * 2;
            if (mv[c0]     > 0.5f) { s[nt][0] = -1.0e30f; s[nt][2] = -1.0e30f; }
            if (mv[c0 + 1] > 0.5f) { s[nt][1] = -1.0e30f; s[nt][3] = -1.0e30f; }
        }

        float mt0 = -3.0e38f, mt1 = -3.0e38f;
#pragma unroll
        for (int nt = 0; nt < 8; nt++) {
            mt0 = fmaxf(mt0, fmaxf(s[nt][0], s[nt][1]));
            mt1 = fmaxf(mt1, fmaxf(s[nt][2], s[nt][3]));
        }
        mt0 = fmaxf(mt0, __shfl_xor_sync(0xffffffffu, mt0, 1));
        mt0 = fmaxf(mt0, __shfl_xor_sync(0xffffffffu, mt0, 2));
        mt1 = fmaxf(mt1, __shfl_xor_sync(0xffffffffu, mt1, 1));
        mt1 = fmaxf(mt1, __shfl_xor_sync(0xffffffffu, mt1, 2));

        const float m_new0 = fmaxf(m_run0, mt0);
        const float m_new1 = fmaxf(m_run1, mt1);
        const float alpha0 = exp2f(m_run0 - m_new0);
        const float alpha1 = exp2f(m_run1 - m_new1);

#pragma unroll
        for (int nt = 0; nt < 8; nt++) {
            o[nt][0] *= alpha0; o[nt][1] *= alpha0;
            o[nt][2] *= alpha1; o[nt][3] *= alpha1;
        }

        float lt0 = 0.f, lt1 = 0.f;
#pragma unroll
        for (int nt = 0; nt < 8; nt++) {
            float p0 = exp2f(s[nt][0] - m_new0);
            float p1 = exp2f(s[nt][1] - m_new0);
            float p2 = exp2f(s[nt][2] - m_new1);
            float p3 = exp2f(s[nt][3] - m_new1);
            s[nt][0] = p0; s[nt][1] = p1; s[nt][2] = p2; s[nt][3] = p3;
            lt0 += p0 + p1; lt1 += p2 + p3;
        }
        lt0 += __shfl_xor_sync(0xffffffffu, lt0, 1);
        lt0 += __shfl_xor_sync(0xffffffffu, lt0, 2);
        lt1 += __shfl_xor_sync(0xffffffffu, lt1, 1);
        lt1 += __shfl_xor_sync(0xffffffffu, lt1, 2);

        l_run0 = l_run0 * alpha0 + lt0;
        l_run1 = l_run1 * alpha1 + lt1;
        m_run0 = m_new0;
        m_run1 = m_new1;

#pragma unroll
        for (int kc = 0; kc < 4; kc++) {
            const float* sa = s[2 * kc];
            const float* sc = s[2 * kc + 1];
            uint32_t ph[4], pl[4];
            ph[0] = pack_bf2(sa[0], sa[1]);
            ph[1] = pack_bf2(sa[2], sa[3]);
            ph[2] = pack_bf2(sc[0], sc[1]);
            ph[3] = pack_bf2(sc[2], sc[3]);
            pl[0] = pack_bf2(bf_res(sa[0]), bf_res(sa[1]));
            pl[1] = pack_bf2(bf_res(sa[2]), bf_res(sa[3]));
            pl[2] = pack_bf2(bf_res(sc[0]), bf_res(sc[1]));
            pl[3] = pack_bf2(bf_res(sc[2]), bf_res(sc[3]));

            const uint32_t rv = rowV + kc * 16;
#pragma unroll
            for (int dp = 0; dp < 4; dp++) {
                const uint32_t cV = ((2 * dp + hiV) ^ (rv & 7)) << 4;
                uint32_t vh4[4], vl4[4];
                LDSM_X4_T(vh4, svh + rv * 128 + cV);
                LDSM_X4_T(vl4, svl + rv * 128 + cV);
                MMA_BF16(o[dp * 2], ph, vh4[0], vh4[1]);
                MMA_BF16(o[dp * 2], pl, vh4[0], vh4[1]);
                MMA_BF16(o[dp * 2], ph, vl4[0], vl4[1]);
                MMA_BF16(o[dp * 2 + 1], ph, vh4[2], vh4[3]);
                MMA_BF16(o[dp * 2 + 1], pl, vh4[2], vh4[3]);
                MMA_BF16(o[dp * 2 + 1], ph, vl4[2], vl4[3]);
            }
        }
        __syncthreads();
    }
#undef ISSUE_KV

    // normalize + write (hi, lo) bf16 directly
    const float inv0 = 1.0f / l_run0;
    const float inv1 = 1.0f / l_run1;
    const int r0 = qbase + w * 16 + (lane >> 2);
#pragma unroll
    for (int nt = 0; nt < 8; nt++) {
        const int col = h * HD + nt * 8 + (lane & 3) * 2;
        float v00 = o[nt][0] * inv0, v01 = o[nt][1] * inv0;
        float v10 = o[nt][2] * inv1, v11 = o[nt][3] * inv1;
        __nv_bfloat16 h00 = __float2bfloat16(v00), h01 = __float2bfloat16(v01);
        __nv_bfloat16 h10 = __float2bfloat16(v10), h11 = __float2bfloat16(v11);
        size_t o0 = (size_t)(b * SEQ + r0) * DIM + col;
        size_t o1 = (size_t)(b * SEQ + r0 + 8) * DIM + col;
        *(__nv_bfloat162*)(AOh + o0) = __nv_bfloat162(h00, h01);
        *(__nv_bfloat162*)(AOh + o1) = __nv_bfloat162(h10, h11);
        *(__nv_bfloat162*)(AOl + o0) =
            __nv_bfloat162(__float2bfloat16(v00 - __bfloat162float(h00)),
                           __float2bfloat16(v01 - __bfloat162float(h01)));
        *(__nv_bfloat162*)(AOl + o1) =
            __nv_bfloat162(__float2bfloat16(v10 - __bfloat162float(h10)),
                           __float2bfloat16(v11 - __bfloat162float(h11)));
    }
}

// ---------------------------------------------------------------------------
// Launch — single stream (graph-capture safe; no streams/events)
// ---------------------------------------------------------------------------
extern "C" void kernel_launch(void* const* d_in, const int* in_sizes, int n_in,
                              void* d_out, int out_size)
{
    const float* x    = (const float*)d_in[0];
    const int*   mask = (const int*)  d_in[1];
    const float* Wq   = (const float*)d_in[2];
    const float* bq   = (const float*)d_in[3];
    const float* Wk   = (const float*)d_in[4];
    const float* bk   = (const float*)d_in[5];
    const float* Wv   = (const float*)d_in[6];
    const float* bv   = (const float*)d_in[7];
    const float* Wf   = (const float*)d_in[8];
    const float* bf   = (const float*)d_in[9];
    float* out = (float*)d_out;

    __nv_bfloat16 *xh, *xl, *xch, *xcl;
    __nv_bfloat16 *wqh, *wql, *wkh, *wkl, *wvh, *wvl, *wfh, *wfl;
    __nv_bfloat16 *qh, *ql, *kh, *kl, *vh, *vl;
    int *gidx, *cnts, *mskc;
    cudaGetSymbolAddress((void**)&xh,  g_xh);
    cudaGetSymbolAddress((void**)&xl,  g_xl);
    cudaGetSymbolAddress((void**)&xch, g_xch);
    cudaGetSymbolAddress((void**)&xcl, g_xcl);
    cudaGetSymbolAddress((void**)&wqh, g_wqh);
    cudaGetSymbolAddress((void**)&wql, g_wql);
    cudaGetSymbolAddress((void**)&wkh, g_wkh);
    cudaGetSymbolAddress((void**)&wkl, g_wkl);
    cudaGetSymbolAddress((void**)&wvh, g_wvh);
    cudaGetSymbolAddress((void**)&wvl, g_wvl);
    cudaGetSymbolAddress((void**)&wfh, g_wfh);
    cudaGetSymbolAddress((void**)&wfl, g_wfl);
    cudaGetSymbolAddress((void**)&qh,  g_qh);
    cudaGetSymbolAddress((void**)&ql,  g_ql);
    cudaGetSymbolAddress((void**)&kh,  g_kh);
    cudaGetSymbolAddress((void**)&kl,  g_kl);
    cudaGetSymbolAddress((void**)&vh,  g_vh);
    cudaGetSymbolAddress((void**)&vl,  g_vl);
    cudaGetSymbolAddress((void**)&gidx, g_gidx);
    cudaGetSymbolAddress((void**)&cnts, g_cnts);
    cudaGetSymbolAddress((void**)&mskc, g_mskc);

    static bool attr_set = false;
    if (!attr_set) {
        cudaFuncSetAttribute(gemm_mma_kernel,
                             cudaFuncAttributeMaxDynamicSharedMemorySize, GEMM_SMEM);
        cudaFuncSetAttribute(attn_mma_kernel,
                             cudaFuncAttributeMaxDynamicSharedMemorySize, ATTN_SMEM);
        attr_set = true;
    }

    const int n4 = MTOT * DIM / 4;
    const dim3 trb(32, 8);
    const dim3 ggrid(DIM / 128, MTOT / 128);

    // prologue: scan + split + weight prep + gather
    mask_scan_kernel<<<BSZ, 1024>>>(mask, gidx, cnts, mskc);
    split_kernel<<<(n4 + 255) / 256, 256>>>(x, xh, xl, n4);
    trsplit4_kernel<<<dim3(32, 32, 4), trb>>>(
        Wq, Wk, Wv, Wf, wqh, wql, wkh, wkl, wvh, wvl, wfh, wfl);
    gather_kernel<<<dim3(SEQ, BSZ), 256>>>(xh, xl, xch, xcl, gidx, cnts);

    // projections (Q scale = 1/8 * log2e folded for base-2 softmax)
    gemm_mma_kernel<<<ggrid, 256, GEMM_SMEM>>>(xh, xl, wqh, wql, bq,
                                               nullptr, qh, ql, 1,
                                               0.125f * LOG2E, nullptr);
    gemm_mma_kernel<<<ggrid, 256, GEMM_SMEM>>>(xch, xcl, wkh, wkl, bk,
                                               nullptr, kh, kl, 1, 1.0f, cnts);
    gemm_mma_kernel<<<ggrid, 256, GEMM_SMEM>>>(xch, xcl, wvh, wvl, bv,
                                               nullptr, vh, vl, 1, 1.0f, cnts);

    // attention writes (hi,lo) directly into xh/xl (x no longer needed)
    attn_mma_kernel<<<dim3(SEQ / A_BM, NH, BSZ), 256, ATTN_SMEM>>>(
        qh, ql, kh, kl, vh, vl, mskc, cnts, xh, xl);

    // final projection
    gemm_mma_kernel<<<ggrid, 256, GEMM_SMEM>>>(xh, xl, wfh, wfl, bf,
                                               out, nullptr, nullptr, 0, 1.0f, nullptr);
}